// round 1
// baseline (speedup 1.0000x reference)
#include <cuda_runtime.h>

// ---------------------------------------------------------------------------
// SSD head: 6x fused (loc+conf) 3x3 SAME conv as implicit GEMM (fp32),
// writing raw conv outputs directly into the final [B, P, 25] layout,
// followed by an in-place decode (boxes) + softmax (scores) kernel.
// ---------------------------------------------------------------------------

#define BM 64
#define BN 128
#define KC 16
#define NTHREADS 128
#define NUM_PRIORS 11640
#define BATCH 32

__global__ __launch_bounds__(NTHREADS) void conv_head_kernel(
    const float* __restrict__ feat,
    const float* __restrict__ loc_w, const float* __restrict__ loc_b,
    const float* __restrict__ conf_w, const float* __restrict__ conf_b,
    float* __restrict__ out,
    int C, int F, int N, int prior_offset)
{
    const int K = C * 9;          // divisible by 16 for all stages
    const int FF = F * F;

    __shared__ __align__(16) float As[KC][BM];       // k-major weights
    __shared__ __align__(16) float Bs[KC][BN];       // k-major im2col patch

    const int tid = threadIdx.x;
    const int tx = tid & 15;      // 0..15 -> n dimension (8 each)
    const int ty = tid >> 4;      // 0..7  -> m dimension (8 each)
    const int bm = blockIdx.y * BM;
    const int bn = blockIdx.x * BN;

    float acc[8][8];
    #pragma unroll
    for (int i = 0; i < 8; i++)
        #pragma unroll
        for (int j = 0; j < 8; j++) acc[i][j] = 0.f;

    // ---- A-tile load mapping: each thread loads 8 consecutive k's for one m
    const int a_m = tid >> 1;            // 0..63
    const int a_k = (tid & 1) * 8;       // 0 or 8
    const int m_glob_a = bm + a_m;
    const float* wptr = nullptr;
    if (m_glob_a < 24)       wptr = loc_w  + (size_t)m_glob_a * K;
    else if (m_glob_a < 150) wptr = conf_w + (size_t)(m_glob_a - 24) * K;

    // ---- B-tile load mapping: each thread owns one n-column, all 16 k's
    const int b_n = tid;                 // 0..127
    const int n_glob_b = bn + b_n;
    const bool n_ok = (n_glob_b < N);
    int bb = 0, yy = 0, xx = 0;
    if (n_ok) {
        bb = n_glob_b / FF;
        int r = n_glob_b - bb * FF;
        yy = r / F;
        xx = r - yy * F;
    }
    const float* fbase = feat + (size_t)bb * C * FF;

    for (int k_base = 0; k_base < K; k_base += KC) {
        // load A (weights): coalesced float4 along k, transposed store
        float4 av0 = make_float4(0.f, 0.f, 0.f, 0.f);
        float4 av1 = make_float4(0.f, 0.f, 0.f, 0.f);
        if (wptr) {
            av0 = *reinterpret_cast<const float4*>(wptr + k_base + a_k);
            av1 = *reinterpret_cast<const float4*>(wptr + k_base + a_k + 4);
        }
        As[a_k + 0][a_m] = av0.x;
        As[a_k + 1][a_m] = av0.y;
        As[a_k + 2][a_m] = av0.z;
        As[a_k + 3][a_m] = av0.w;
        As[a_k + 4][a_m] = av1.x;
        As[a_k + 5][a_m] = av1.y;
        As[a_k + 6][a_m] = av1.z;
        As[a_k + 7][a_m] = av1.w;

        // load B (on-the-fly im2col gather): coalesced across threads per k
        #pragma unroll
        for (int k = 0; k < KC; k++) {
            int kg = k_base + k;
            float v = 0.f;
            if (n_ok) {
                int c  = kg / 9;
                int kk = kg - c * 9;
                int ky = kk / 3;
                int kx = kk - ky * 3;
                int iy = yy + ky - 1;
                int ix = xx + kx - 1;
                if ((unsigned)iy < (unsigned)F && (unsigned)ix < (unsigned)F)
                    v = fbase[((size_t)c * F + iy) * F + ix];
            }
            Bs[k][b_n] = v;
        }
        __syncthreads();

        // 8x8 outer-product micro-kernel: 64B LDS per 64 FFMA (balanced)
        #pragma unroll
        for (int k = 0; k < KC; k++) {
            float4 a0 = *reinterpret_cast<const float4*>(&As[k][ty * 8]);
            float4 a1 = *reinterpret_cast<const float4*>(&As[k][ty * 8 + 4]);
            float4 b0 = *reinterpret_cast<const float4*>(&Bs[k][tx * 8]);
            float4 b1 = *reinterpret_cast<const float4*>(&Bs[k][tx * 8 + 4]);
            float a[8] = {a0.x, a0.y, a0.z, a0.w, a1.x, a1.y, a1.z, a1.w};
            float b[8] = {b0.x, b0.y, b0.z, b0.w, b1.x, b1.y, b1.z, b1.w};
            #pragma unroll
            for (int i = 0; i < 8; i++)
                #pragma unroll
                for (int j = 0; j < 8; j++)
                    acc[i][j] += a[i] * b[j];
        }
        __syncthreads();
    }

    // ---- epilogue: scatter into final [b, prior, col] layout
    #pragma unroll
    for (int i = 0; i < 8; i++) {
        int m = bm + ty * 8 + i;
        if (m >= 150) continue;
        float bias;
        int col, pic;                    // output column, prior-in-cell
        if (m < 24) { bias = loc_b[m];       col = m & 3;            pic = m >> 2; }
        else        { int mc = m - 24;
                      bias = conf_b[mc];     col = 4 + (mc % 21);    pic = mc / 21; }
        #pragma unroll
        for (int j = 0; j < 8; j++) {
            int n = bn + tx * 8 + j;
            if (n >= N) continue;
            int b = n / FF;
            int r = n - b * FF;
            int p = prior_offset + r * 6 + pic;
            out[((size_t)b * NUM_PRIORS + p) * 25 + col] = acc[i][j] + bias;
        }
    }
}

__global__ __launch_bounds__(256) void decode_kernel(
    float* __restrict__ out, const float* __restrict__ priors, int total)
{
    int idx = blockIdx.x * blockDim.x + threadIdx.x;
    if (idx >= total) return;
    int p = idx % NUM_PRIORS;
    float* o = out + (size_t)idx * 25;

    float4 pr = *reinterpret_cast<const float4*>(priors + (size_t)p * 4); // cx,cy,w,h
    float lx = o[0], ly = o[1], lw = o[2], lh = o[3];
    float cx = pr.x + lx * 0.1f * pr.z;
    float cy = pr.y + ly * 0.1f * pr.w;
    float w  = pr.z * __expf(lw * 0.2f) ;
    float h  = pr.w * __expf(lh * 0.2f) ;
    // use precise expf for safety on boxes
    w = pr.z * expf(lw * 0.2f);
    h = pr.w * expf(lh * 0.2f);
    float minx = cx - w * 0.5f;
    float miny = cy - h * 0.5f;
    o[0] = minx; o[1] = miny; o[2] = minx + w; o[3] = miny + h;

    // softmax over 21 classes
    float v[21];
    float mx = -1e30f;
    #pragma unroll
    for (int c = 0; c < 21; c++) { v[c] = o[4 + c]; mx = fmaxf(mx, v[c]); }
    float s = 0.f;
    #pragma unroll
    for (int c = 0; c < 21; c++) { v[c] = expf(v[c] - mx); s += v[c]; }
    float inv = 1.f / s;
    #pragma unroll
    for (int c = 0; c < 21; c++) o[4 + c] = v[c] * inv;
}

extern "C" void kernel_launch(void* const* d_in, const int* in_sizes, int n_in,
                              void* d_out, int out_size)
{
    const float* feat[6];
    const float* lw[6];
    const float* lb[6];
    const float* cw[6];
    const float* cb[6];
    const float* priors;

    // Detect input ordering: interleaved (setup_inputs dict order) vs grouped
    // (reference signature order). Interleaved has loc_b0 (24 elems) at idx 2.
    bool interleaved = (n_in == 31) && (in_sizes[2] == 24);
    if (interleaved) {
        for (int s = 0; s < 6; s++) {
            feat[s] = (const float*)d_in[s * 5 + 0];
            lw[s]   = (const float*)d_in[s * 5 + 1];
            lb[s]   = (const float*)d_in[s * 5 + 2];
            cw[s]   = (const float*)d_in[s * 5 + 3];
            cb[s]   = (const float*)d_in[s * 5 + 4];
        }
        priors = (const float*)d_in[30];
    } else {
        for (int s = 0; s < 6; s++) {
            feat[s] = (const float*)d_in[s];
            lw[s]   = (const float*)d_in[6 + s];
            lb[s]   = (const float*)d_in[12 + s];
            cw[s]   = (const float*)d_in[18 + s];
            cb[s]   = (const float*)d_in[24 + s];
        }
        priors = (const float*)d_in[30];
    }

    static const int Cs[6]   = {512, 1024, 512, 256, 256, 256};
    static const int Fs[6]   = {38, 19, 10, 5, 3, 1};
    static const int poff[6] = {0, 8664, 10830, 11430, 11580, 11634};

    float* out = (float*)d_out;

    for (int s = 0; s < 6; s++) {
        int N = BATCH * Fs[s] * Fs[s];
        dim3 grid((N + BN - 1) / BN, (150 + BM - 1) / BM);
        conv_head_kernel<<<grid, NTHREADS>>>(
            feat[s], lw[s], lb[s], cw[s], cb[s], out,
            Cs[s], Fs[s], N, poff[s]);
    }

    int total = BATCH * NUM_PRIORS;
    decode_kernel<<<(total + 255) / 256, 256>>>(out, priors, total);
}

// round 2
// speedup vs baseline: 2.3928x; 2.3928x over previous
#include <cuda_runtime.h>

// ---------------------------------------------------------------------------
// SSD head, round 2: ALL six (loc+conf) 3x3 convs fused into ONE kernel
// launch (static block->work map), split-K with atomicAdd into pre-zeroed
// output, kk-major K ordering with a one-shot weight transpose so the im2col
// gather is a single strided stream per k-tile, register-prefetch double
// buffering. Decode (boxes + softmax) stays a second kernel.
// ---------------------------------------------------------------------------

#define KC 16
#define BM 64
#define BN 128
#define NTHREADS 128
#define WSTRIDE 192
#define NUM_PRIORS 11640
#define BATCH 32

// ---- static stage tables (compile-time) ----
__device__ __constant__ int c_C[6]      = {512, 1024, 512, 256, 256, 256};
__device__ __constant__ int c_logC[6]   = {9, 10, 9, 8, 8, 8};
__device__ __constant__ int c_F[6]      = {38, 19, 10, 5, 3, 1};
__device__ __constant__ int c_N[6]      = {46208, 11552, 3200, 800, 288, 32};
__device__ __constant__ int c_K[6]      = {4608, 9216, 4608, 2304, 2304, 2304};
__device__ __constant__ int c_kchunks[6]= {2, 4, 2, 2, 4, 8};
__device__ __constant__ int c_chunkK[6] = {2304, 2304, 2304, 1152, 576, 288};
__device__ __constant__ int c_blkoff[7] = {0, 2166, 3258, 3408, 3450, 3486, 3510};
__device__ __constant__ int c_wtrow[7]  = {0, 4608, 13824, 18432, 20736, 23040, 25344};
__device__ __constant__ int c_poff[6]   = {0, 8664, 10830, 11430, 11580, 11634};

#define TOTAL_BLOCKS 3510
#define TOTAL_WROWS 25344

// transposed weights, layout [k'][m] with k' = kk*C + c, row stride WSTRIDE.
// zero-initialized at module load; padding columns (150..191) stay zero.
__device__ float g_wt[(size_t)TOTAL_WROWS * WSTRIDE];

struct WParams { const float* lw[6]; const float* cw[6]; };
struct CParams { const float* feat[6]; const float* lb[6]; const float* cb[6]; };

// ---------------------------------------------------------------------------
__global__ __launch_bounds__(256) void zero_out_kernel(float4* o, int n4)
{
    int i = blockIdx.x * blockDim.x + threadIdx.x;
    if (i < n4) o[i] = make_float4(0.f, 0.f, 0.f, 0.f);
}

// ---------------------------------------------------------------------------
__global__ __launch_bounds__(256) void transpose_weights_kernel(WParams P)
{
    int gid = blockIdx.x * blockDim.x + threadIdx.x;
    if (gid >= TOTAL_WROWS * 160) return;
    int row = gid / 160;
    int col = gid - row * 160;
    if (col >= 150) return;

    int s = 0;
    #pragma unroll
    for (int i = 1; i < 6; i++) if (row >= c_wtrow[i]) s = i;
    int kp = row - c_wtrow[s];
    int kk = kp >> c_logC[s];
    int c  = kp & (c_C[s] - 1);
    int Ks = c_K[s];

    float v;
    if (col < 24) v = P.lw[s][(size_t)col * Ks + c * 9 + kk];
    else          v = P.cw[s][(size_t)(col - 24) * Ks + c * 9 + kk];
    g_wt[(size_t)row * WSTRIDE + col] = v;
}

// ---------------------------------------------------------------------------
__global__ __launch_bounds__(NTHREADS, 3) void fused_conv_kernel(
    CParams P, float* __restrict__ out)
{
    const int bid = blockIdx.x;
    int s = 0;
    #pragma unroll
    for (int i = 1; i < 6; i++) if (bid >= c_blkoff[i]) s = i;

    const int local = bid - c_blkoff[s];
    const int kch   = c_kchunks[s];
    const int kc    = local % kch;
    const int rem   = local / kch;
    const int mt    = rem % 3;
    const int nt    = rem / 3;

    const int C    = c_C[s];
    const int logC = c_logC[s];
    const int F    = c_F[s];
    const int FF   = F * F;
    const int N    = c_N[s];
    const int bm   = mt * BM;
    const int bn   = nt * BN;
    const int wrow0 = c_wtrow[s];
    const float* __restrict__ feat = P.feat[s];

    __shared__ __align__(16) float As[KC][BM];
    __shared__ __align__(16) float Bs[KC][BN];

    const int tid = threadIdx.x;
    const int tx = tid & 15;
    const int ty = tid >> 4;

    float acc[8][8];
    #pragma unroll
    for (int i = 0; i < 8; i++)
        #pragma unroll
        for (int j = 0; j < 8; j++) acc[i][j] = 0.f;

    // ---- B column geometry (one output pixel per thread) ----
    const int n_glob = bn + tid;
    const bool n_ok = (n_glob < N);
    int bb = 0, yy = 0, xx = 0;
    if (n_ok) {
        bb = n_glob / FF;
        int r = n_glob - bb * FF;
        yy = r / F;
        xx = r - yy * F;
    }
    const float* fb0 = feat + (size_t)bb * C * FF;

    // ---- A load mapping: thread -> (k row, 8 m's), direct float4 ----
    const int a_krow = tid >> 3;
    const int a_m4   = (tid & 7) << 3;
    const float* wbase = g_wt + (size_t)(wrow0 + a_krow) * WSTRIDE + bm + a_m4;

    const int k0 = kc * c_chunkK[s];
    const int ntile = c_chunkK[s] / KC;

    float4 apre0, apre1;
    float bpre[KC];

    // ---- prefetch helper (as a macro-like lambda) ----
    auto prefetch = [&](int k_base) {
        const float* wp = wbase + (size_t)k_base * WSTRIDE;
        apre0 = *reinterpret_cast<const float4*>(wp);
        apre1 = *reinterpret_cast<const float4*>(wp + 4);
        int kk = k_base >> logC;
        int c0 = k_base & (C - 1);
        int ky = kk / 3;
        int kx = kk - ky * 3;
        int iy = yy + ky - 1;
        int ix = xx + kx - 1;
        bool v = n_ok && ((unsigned)iy < (unsigned)F) && ((unsigned)ix < (unsigned)F);
        const float* bp = fb0 + (size_t)c0 * FF + iy * F + ix;
        #pragma unroll
        for (int k = 0; k < KC; k++)
            bpre[k] = v ? __ldg(bp + (size_t)k * FF) : 0.f;
    };

    prefetch(k0);

    for (int t = 0; t < ntile; t++) {
        // commit prefetched tile to smem
        *reinterpret_cast<float4*>(&As[a_krow][a_m4])     = apre0;
        *reinterpret_cast<float4*>(&As[a_krow][a_m4 + 4]) = apre1;
        #pragma unroll
        for (int k = 0; k < KC; k++) Bs[k][tid] = bpre[k];
        __syncthreads();

        if (t + 1 < ntile) prefetch(k0 + (t + 1) * KC);

        #pragma unroll
        for (int k = 0; k < KC; k++) {
            float4 a0 = *reinterpret_cast<const float4*>(&As[k][ty * 8]);
            float4 a1 = *reinterpret_cast<const float4*>(&As[k][ty * 8 + 4]);
            float4 b0 = *reinterpret_cast<const float4*>(&Bs[k][tx * 8]);
            float4 b1 = *reinterpret_cast<const float4*>(&Bs[k][tx * 8 + 4]);
            float a[8] = {a0.x, a0.y, a0.z, a0.w, a1.x, a1.y, a1.z, a1.w};
            float b[8] = {b0.x, b0.y, b0.z, b0.w, b1.x, b1.y, b1.z, b1.w};
            #pragma unroll
            for (int i = 0; i < 8; i++)
                #pragma unroll
                for (int j = 0; j < 8; j++)
                    acc[i][j] += a[i] * b[j];
        }
        __syncthreads();
    }

    // ---- epilogue: atomic scatter into [b, prior, col] (out pre-zeroed) ----
    const float* lb = P.lb[s];
    const float* cb = P.cb[s];
    const int poff = c_poff[s];
    #pragma unroll
    for (int i = 0; i < 8; i++) {
        int m = bm + ty * 8 + i;
        if (m >= 150) continue;
        float bias = 0.f;
        int col, pic;
        if (m < 24) { if (kc == 0) bias = lb[m];      col = m & 3;         pic = m >> 2; }
        else        { int mc = m - 24;
                      if (kc == 0) bias = cb[mc];     col = 4 + (mc % 21); pic = mc / 21; }
        #pragma unroll
        for (int j = 0; j < 8; j++) {
            int n = bn + tx * 8 + j;
            if (n >= N) continue;
            int b = n / FF;
            int r = n - b * FF;
            int p = poff + r * 6 + pic;
            atomicAdd(&out[((size_t)b * NUM_PRIORS + p) * 25 + col], acc[i][j] + bias);
        }
    }
}

// ---------------------------------------------------------------------------
__global__ __launch_bounds__(256) void decode_kernel(
    float* __restrict__ out, const float* __restrict__ priors, int total)
{
    int idx = blockIdx.x * blockDim.x + threadIdx.x;
    if (idx >= total) return;
    int p = idx % NUM_PRIORS;
    float* o = out + (size_t)idx * 25;

    float4 pr = *reinterpret_cast<const float4*>(priors + (size_t)p * 4); // cx,cy,w,h
    float lx = o[0], ly = o[1], lw = o[2], lh = o[3];
    float cx = pr.x + lx * 0.1f * pr.z;
    float cy = pr.y + ly * 0.1f * pr.w;
    float w  = pr.z * expf(lw * 0.2f);
    float h  = pr.w * expf(lh * 0.2f);
    float minx = cx - w * 0.5f;
    float miny = cy - h * 0.5f;
    o[0] = minx; o[1] = miny; o[2] = minx + w; o[3] = miny + h;

    float v[21];
    float mx = -1e30f;
    #pragma unroll
    for (int c = 0; c < 21; c++) { v[c] = o[4 + c]; mx = fmaxf(mx, v[c]); }
    float ssum = 0.f;
    #pragma unroll
    for (int c = 0; c < 21; c++) { v[c] = expf(v[c] - mx); ssum += v[c]; }
    float inv = 1.f / ssum;
    #pragma unroll
    for (int c = 0; c < 21; c++) o[4 + c] = v[c] * inv;
}

// ---------------------------------------------------------------------------
extern "C" void kernel_launch(void* const* d_in, const int* in_sizes, int n_in,
                              void* d_out, int out_size)
{
    CParams cp;
    WParams wp;
    const float* priors;

    bool interleaved = (n_in == 31) && (in_sizes[2] == 24);
    if (interleaved) {
        for (int s = 0; s < 6; s++) {
            cp.feat[s] = (const float*)d_in[s * 5 + 0];
            wp.lw[s]   = (const float*)d_in[s * 5 + 1];
            cp.lb[s]   = (const float*)d_in[s * 5 + 2];
            wp.cw[s]   = (const float*)d_in[s * 5 + 3];
            cp.cb[s]   = (const float*)d_in[s * 5 + 4];
        }
        priors = (const float*)d_in[30];
    } else {
        for (int s = 0; s < 6; s++) {
            cp.feat[s] = (const float*)d_in[s];
            wp.lw[s]   = (const float*)d_in[6 + s];
            cp.lb[s]   = (const float*)d_in[12 + s];
            wp.cw[s]   = (const float*)d_in[18 + s];
            cp.cb[s]   = (const float*)d_in[24 + s];
        }
        priors = (const float*)d_in[30];
    }

    float* out = (float*)d_out;

    // 1) zero output (atomicAdd accumulation target)
    int n4 = out_size / 4;
    zero_out_kernel<<<(n4 + 255) / 256, 256>>>((float4*)out, n4);

    // 2) transpose weights into kk-major [k'][m] scratch
    int tw_total = TOTAL_WROWS * 160;
    transpose_weights_kernel<<<(tw_total + 255) / 256, 256>>>(wp);

    // 3) all six convs in one launch
    fused_conv_kernel<<<TOTAL_BLOCKS, NTHREADS>>>(cp, out);

    // 4) decode + softmax in place
    int total = BATCH * NUM_PRIORS;
    decode_kernel<<<(total + 255) / 256, 256>>>(out, priors, total);
}

// round 3
// speedup vs baseline: 2.6171x; 1.0937x over previous
#include <cuda_runtime.h>

// ---------------------------------------------------------------------------
// SSD head, round 3: same fused single-launch implicit-GEMM conv as round 2,
// but the 8x8 micro-kernel now uses packed f32x2 FMA (PTX fma.rn.f32x2 ->
// SASS FFMA2), halving fma-pipe issue count, which was the round-2 ceiling.
// ---------------------------------------------------------------------------

#define KC 16
#define BM 64
#define BN 128
#define NTHREADS 128
#define WSTRIDE 192
#define NUM_PRIORS 11640
#define BATCH 32

__device__ __constant__ int c_C[6]      = {512, 1024, 512, 256, 256, 256};
__device__ __constant__ int c_logC[6]   = {9, 10, 9, 8, 8, 8};
__device__ __constant__ int c_F[6]      = {38, 19, 10, 5, 3, 1};
__device__ __constant__ int c_N[6]      = {46208, 11552, 3200, 800, 288, 32};
__device__ __constant__ int c_K[6]      = {4608, 9216, 4608, 2304, 2304, 2304};
__device__ __constant__ int c_kchunks[6]= {2, 4, 2, 2, 4, 8};
__device__ __constant__ int c_chunkK[6] = {2304, 2304, 2304, 1152, 576, 288};
__device__ __constant__ int c_blkoff[7] = {0, 2166, 3258, 3408, 3450, 3486, 3510};
__device__ __constant__ int c_wtrow[7]  = {0, 4608, 13824, 18432, 20736, 23040, 25344};
__device__ __constant__ int c_poff[6]   = {0, 8664, 10830, 11430, 11580, 11634};

#define TOTAL_BLOCKS 3510
#define TOTAL_WROWS 25344

__device__ float g_wt[(size_t)TOTAL_WROWS * WSTRIDE];

struct WParams { const float* lw[6]; const float* cw[6]; };
struct CParams { const float* feat[6]; const float* lb[6]; const float* cb[6]; };

// ---- packed f32x2 helpers -------------------------------------------------
__device__ __forceinline__ unsigned long long pack2(float x) {
    unsigned long long r;
    asm("mov.b64 %0, {%1, %1};" : "=l"(r) : "f"(x));
    return r;
}
__device__ __forceinline__ void fma2(unsigned long long& d,
                                     unsigned long long a,
                                     unsigned long long b) {
    asm("fma.rn.f32x2 %0, %1, %2, %0;" : "+l"(d) : "l"(a), "l"(b));
}
__device__ __forceinline__ void unpack2(unsigned long long v, float& lo, float& hi) {
    asm("mov.b64 {%0, %1}, %2;" : "=f"(lo), "=f"(hi) : "l"(v));
}

// ---------------------------------------------------------------------------
__global__ __launch_bounds__(256) void zero_out_kernel(float4* o, int n4)
{
    int i = blockIdx.x * blockDim.x + threadIdx.x;
    if (i < n4) o[i] = make_float4(0.f, 0.f, 0.f, 0.f);
}

// ---------------------------------------------------------------------------
__global__ __launch_bounds__(256) void transpose_weights_kernel(WParams P)
{
    int gid = blockIdx.x * blockDim.x + threadIdx.x;
    if (gid >= TOTAL_WROWS * 160) return;
    int row = gid / 160;
    int col = gid - row * 160;
    if (col >= 150) return;

    int s = 0;
    #pragma unroll
    for (int i = 1; i < 6; i++) if (row >= c_wtrow[i]) s = i;
    int kp = row - c_wtrow[s];
    int kk = kp >> c_logC[s];
    int c  = kp & (c_C[s] - 1);
    int Ks = c_K[s];

    float v;
    if (col < 24) v = P.lw[s][(size_t)col * Ks + c * 9 + kk];
    else          v = P.cw[s][(size_t)(col - 24) * Ks + c * 9 + kk];
    g_wt[(size_t)row * WSTRIDE + col] = v;
}

// ---------------------------------------------------------------------------
__global__ __launch_bounds__(NTHREADS, 3) void fused_conv_kernel(
    CParams P, float* __restrict__ out)
{
    const int bid = blockIdx.x;
    int s = 0;
    #pragma unroll
    for (int i = 1; i < 6; i++) if (bid >= c_blkoff[i]) s = i;

    const int local = bid - c_blkoff[s];
    const int kch   = c_kchunks[s];
    const int kc    = local % kch;
    const int rem   = local / kch;
    const int mt    = rem % 3;
    const int nt    = rem / 3;

    const int C    = c_C[s];
    const int logC = c_logC[s];
    const int F    = c_F[s];
    const int FF   = F * F;
    const int N    = c_N[s];
    const int bm   = mt * BM;
    const int bn   = nt * BN;
    const int wrow0 = c_wtrow[s];
    const float* __restrict__ feat = P.feat[s];

    __shared__ __align__(16) float As[KC][BM];
    __shared__ __align__(16) float Bs[KC][BN];

    const int tid = threadIdx.x;
    const int tx = tid & 15;
    const int ty = tid >> 4;

    unsigned long long acc2[8][4];
    #pragma unroll
    for (int i = 0; i < 8; i++)
        #pragma unroll
        for (int j = 0; j < 4; j++) acc2[i][j] = 0ull;

    // ---- B column geometry (one output pixel per thread) ----
    const int n_glob = bn + tid;
    const bool n_ok = (n_glob < N);
    int bb = 0, yy = 0, xx = 0;
    if (n_ok) {
        bb = n_glob / FF;
        int r = n_glob - bb * FF;
        yy = r / F;
        xx = r - yy * F;
    }
    const float* fb0 = feat + (size_t)bb * C * FF;

    // ---- A load mapping: thread -> (k row, 8 m's), direct float4 ----
    const int a_krow = tid >> 3;
    const int a_m4   = (tid & 7) << 3;
    const float* wbase = g_wt + (size_t)(wrow0 + a_krow) * WSTRIDE + bm + a_m4;

    const int k0 = kc * c_chunkK[s];
    const int ntile = c_chunkK[s] / KC;

    float4 apre0, apre1;
    float bpre[KC];

    auto prefetch = [&](int k_base) {
        const float* wp = wbase + (size_t)k_base * WSTRIDE;
        apre0 = *reinterpret_cast<const float4*>(wp);
        apre1 = *reinterpret_cast<const float4*>(wp + 4);
        int kk = k_base >> logC;
        int c0 = k_base & (C - 1);
        int ky = kk / 3;
        int kx = kk - ky * 3;
        int iy = yy + ky - 1;
        int ix = xx + kx - 1;
        bool v = n_ok && ((unsigned)iy < (unsigned)F) && ((unsigned)ix < (unsigned)F);
        const float* bp = fb0 + (size_t)c0 * FF + iy * F + ix;
        #pragma unroll
        for (int k = 0; k < KC; k++)
            bpre[k] = v ? __ldg(bp + (size_t)k * FF) : 0.f;
    };

    prefetch(k0);

    for (int t = 0; t < ntile; t++) {
        *reinterpret_cast<float4*>(&As[a_krow][a_m4])     = apre0;
        *reinterpret_cast<float4*>(&As[a_krow][a_m4 + 4]) = apre1;
        #pragma unroll
        for (int k = 0; k < KC; k++) Bs[k][tid] = bpre[k];
        __syncthreads();

        if (t + 1 < ntile) prefetch(k0 + (t + 1) * KC);

        #pragma unroll
        for (int k = 0; k < KC; k++) {
            float4 a0 = *reinterpret_cast<const float4*>(&As[k][ty * 8]);
            float4 a1 = *reinterpret_cast<const float4*>(&As[k][ty * 8 + 4]);
            ulonglong2 bb0 = *reinterpret_cast<const ulonglong2*>(&Bs[k][tx * 8]);
            ulonglong2 bb1 = *reinterpret_cast<const ulonglong2*>(&Bs[k][tx * 8 + 4]);
            unsigned long long b2[4] = {bb0.x, bb0.y, bb1.x, bb1.y};
            unsigned long long a2[8];
            a2[0] = pack2(a0.x); a2[1] = pack2(a0.y);
            a2[2] = pack2(a0.z); a2[3] = pack2(a0.w);
            a2[4] = pack2(a1.x); a2[5] = pack2(a1.y);
            a2[6] = pack2(a1.z); a2[7] = pack2(a1.w);
            #pragma unroll
            for (int i = 0; i < 8; i++)
                #pragma unroll
                for (int j = 0; j < 4; j++)
                    fma2(acc2[i][j], a2[i], b2[j]);
        }
        __syncthreads();
    }

    // ---- epilogue: atomic scatter into [b, prior, col] (out pre-zeroed) ----
    const float* lb = P.lb[s];
    const float* cb = P.cb[s];
    const int poff = c_poff[s];
    #pragma unroll
    for (int i = 0; i < 8; i++) {
        int m = bm + ty * 8 + i;
        if (m >= 150) continue;
        float bias = 0.f;
        int col, pic;
        if (m < 24) { if (kc == 0) bias = lb[m];      col = m & 3;         pic = m >> 2; }
        else        { int mc = m - 24;
                      if (kc == 0) bias = cb[mc];     col = 4 + (mc % 21); pic = mc / 21; }
        #pragma unroll
        for (int j = 0; j < 4; j++) {
            float vlo, vhi;
            unpack2(acc2[i][j], vlo, vhi);
            #pragma unroll
            for (int h = 0; h < 2; h++) {
                int n = bn + tx * 8 + j * 2 + h;
                if (n >= N) continue;
                int b = n / FF;
                int r = n - b * FF;
                int p = poff + r * 6 + pic;
                atomicAdd(&out[((size_t)b * NUM_PRIORS + p) * 25 + col],
                          (h ? vhi : vlo) + bias);
            }
        }
    }
}

// ---------------------------------------------------------------------------
__global__ __launch_bounds__(256) void decode_kernel(
    float* __restrict__ out, const float* __restrict__ priors, int total)
{
    int idx = blockIdx.x * blockDim.x + threadIdx.x;
    if (idx >= total) return;
    int p = idx % NUM_PRIORS;
    float* o = out + (size_t)idx * 25;

    float4 pr = *reinterpret_cast<const float4*>(priors + (size_t)p * 4);
    float lx = o[0], ly = o[1], lw = o[2], lh = o[3];
    float cx = pr.x + lx * 0.1f * pr.z;
    float cy = pr.y + ly * 0.1f * pr.w;
    float w  = pr.z * expf(lw * 0.2f);
    float h  = pr.w * expf(lh * 0.2f);
    float minx = cx - w * 0.5f;
    float miny = cy - h * 0.5f;
    o[0] = minx; o[1] = miny; o[2] = minx + w; o[3] = miny + h;

    float v[21];
    float mx = -1e30f;
    #pragma unroll
    for (int c = 0; c < 21; c++) { v[c] = o[4 + c]; mx = fmaxf(mx, v[c]); }
    float ssum = 0.f;
    #pragma unroll
    for (int c = 0; c < 21; c++) { v[c] = expf(v[c] - mx); ssum += v[c]; }
    float inv = 1.f / ssum;
    #pragma unroll
    for (int c = 0; c < 21; c++) o[4 + c] = v[c] * inv;
}

// ---------------------------------------------------------------------------
extern "C" void kernel_launch(void* const* d_in, const int* in_sizes, int n_in,
                              void* d_out, int out_size)
{
    CParams cp;
    WParams wp;
    const float* priors;

    bool interleaved = (n_in == 31) && (in_sizes[2] == 24);
    if (interleaved) {
        for (int s = 0; s < 6; s++) {
            cp.feat[s] = (const float*)d_in[s * 5 + 0];
            wp.lw[s]   = (const float*)d_in[s * 5 + 1];
            cp.lb[s]   = (const float*)d_in[s * 5 + 2];
            wp.cw[s]   = (const float*)d_in[s * 5 + 3];
            cp.cb[s]   = (const float*)d_in[s * 5 + 4];
        }
        priors = (const float*)d_in[30];
    } else {
        for (int s = 0; s < 6; s++) {
            cp.feat[s] = (const float*)d_in[s];
            wp.lw[s]   = (const float*)d_in[6 + s];
            cp.lb[s]   = (const float*)d_in[12 + s];
            wp.cw[s]   = (const float*)d_in[18 + s];
            cp.cb[s]   = (const float*)d_in[24 + s];
        }
        priors = (const float*)d_in[30];
    }

    float* out = (float*)d_out;

    int n4 = out_size / 4;
    zero_out_kernel<<<(n4 + 255) / 256, 256>>>((float4*)out, n4);

    int tw_total = TOTAL_WROWS * 160;
    transpose_weights_kernel<<<(tw_total + 255) / 256, 256>>>(wp);

    fused_conv_kernel<<<TOTAL_BLOCKS, NTHREADS>>>(cp, out);

    int total = BATCH * NUM_PRIORS;
    decode_kernel<<<(total + 255) / 256, 256>>>(out, priors, total);
}

// round 5
// speedup vs baseline: 6.5510x; 2.5032x over previous
#include <cuda_runtime.h>
#include <cuda_bf16.h>
#include <stdint.h>

// ---------------------------------------------------------------------------
// SSD head via legacy warp-level mma.sync (bf16, 3-term hi/lo split).
// tcgen05 is unavailable under the harness's compute_103 (non-'a') PTX target,
// so we use the baseline-PTX tensor path: ldmatrix + mma.sync.m16n8k16.
// Per block: 128-pixel tile x 152 padded output channels, K in 64-chunks.
// Weights preprocessed once into a bf16 hi/lo image (kk-major, 144B rows).
// Epilogue: fragments -> smem -> per-pixel bias + box decode + softmax.
// ---------------------------------------------------------------------------

#define NUM_PRIORS 11640
#define NTH 128
#define RS 144                        // smem row stride (bytes): 9 granules -> LDSM conflict-free
#define WTILE (152 * RS)              // 21888
#define WCHUNK (2 * WTILE)            // 43776 (hi + lo)
#define TOTAL_WCHUNKS 396
#define TOTAL_BLOCKS 488
#define A_HI 0
#define A_LO 18432                    // 128*144
#define B_HI 36864
#define B_LO (36864 + WTILE)
#define SMEM_BYTES 80640              // max(A+B = 80640, Dsm = 128*153*4 = 78336)

__device__ __constant__ int d_C[6]    = {512,1024,512,256,256,256};
__device__ __constant__ int d_logC[6] = {9,10,9,8,8,8};
__device__ __constant__ int d_F[6]    = {38,19,10,5,3,1};
__device__ __constant__ int d_FF[6]   = {1444,361,100,25,9,1};
__device__ __constant__ int d_N[6]    = {46208,11552,3200,800,288,32};
__device__ __constant__ int d_nch[6]  = {72,144,72,36,36,36};
__device__ __constant__ int d_wch0[6] = {0,72,216,288,324,360};
__device__ __constant__ int d_poff[6] = {0,8664,10830,11430,11580,11634};
__device__ __constant__ int d_bstart[7] = {0,91,452,477,484,487,488};
__device__ __constant__ int d_border[6] = {1,0,2,3,4,5};

__device__ unsigned char g_wbf[(size_t)TOTAL_WCHUNKS * WCHUNK];

struct WParams { const float* lw[6]; const float* cw[6]; };
struct CParams { const float* feat[6]; const float* lb[6]; const float* cb[6]; };

// ---- PTX helpers ------------------------------------------------------------
__device__ __forceinline__ uint32_t smaddr(const void* p) {
    return (uint32_t)__cvta_generic_to_shared(p);
}
__device__ __forceinline__ void ldsm4(uint32_t* r, uint32_t a) {
    asm volatile("ldmatrix.sync.aligned.m8n8.x4.shared.b16 {%0,%1,%2,%3}, [%4];"
                 : "=r"(r[0]), "=r"(r[1]), "=r"(r[2]), "=r"(r[3]) : "r"(a));
}
__device__ __forceinline__ void ldsm2(uint32_t* r, uint32_t a) {
    asm volatile("ldmatrix.sync.aligned.m8n8.x2.shared.b16 {%0,%1}, [%2];"
                 : "=r"(r[0]), "=r"(r[1]) : "r"(a));
}
__device__ __forceinline__ void mma16816(float* d, const uint32_t* a, const uint32_t* b) {
    asm volatile("mma.sync.aligned.m16n8k16.row.col.f32.bf16.bf16.f32 "
                 "{%0,%1,%2,%3},{%4,%5,%6,%7},{%8,%9},{%0,%1,%2,%3};"
                 : "+f"(d[0]), "+f"(d[1]), "+f"(d[2]), "+f"(d[3])
                 : "r"(a[0]), "r"(a[1]), "r"(a[2]), "r"(a[3]),
                   "r"(b[0]), "r"(b[1]));
}

// ---- weight preprocessing: split bf16 hi/lo, kk-major, 144B row stride ------
__global__ __launch_bounds__(256) void prep_weights(WParams P)
{
    int ch = blockIdx.x;
    int s = 0;
    #pragma unroll
    for (int i = 1; i < 6; i++) if (ch >= d_wch0[i]) s = i;
    int cis = ch - d_wch0[s];
    int C = d_C[s];
    int K = C * 9;
    int k0 = cis * 64;
    int kk = k0 >> d_logC[s];
    int c0 = k0 & (C - 1);
    size_t base = (size_t)ch * WCHUNK;

    for (int e = threadIdx.x; e < 152 * 64; e += blockDim.x) {
        int row = e >> 6;
        int col = e & 63;
        float v = 0.f;
        if (row < 150) {
            int widx = (c0 + col) * 9 + kk;
            v = (row < 24) ? P.lw[s][(size_t)row * K + widx]
                           : P.cw[s][(size_t)(row - 24) * K + widx];
        }
        __nv_bfloat16 h = __float2bfloat16(v);
        __nv_bfloat16 l = __float2bfloat16(v - __bfloat162float(h));
        size_t off = base + (size_t)row * RS + col * 2;
        *(__nv_bfloat16*)(g_wbf + off) = h;
        *(__nv_bfloat16*)(g_wbf + off + WTILE) = l;
    }
}

// ---- main fused kernel --------------------------------------------------------
__global__ __launch_bounds__(NTH, 2) void ssd_hmma_kernel(
    CParams P, const float* __restrict__ priors, float* __restrict__ out)
{
    extern __shared__ __align__(16) unsigned char sm[];
    float* Dsm = (float*)sm;
    const uint32_t smb = smaddr(sm);

    const int tid = threadIdx.x;
    const int wid = tid >> 5;
    const int lane = tid & 31;

    // ---- block -> (stage, pixel tile) ----
    int bid = blockIdx.x;
    int oi = 0;
    #pragma unroll
    for (int i = 1; i < 6; i++) if (bid >= d_bstart[i]) oi = i;
    const int s = d_border[oi];
    const int pix0 = (bid - d_bstart[oi]) * 128;

    const int C = d_C[s], logC = d_logC[s], F = d_F[s], FF = d_FF[s], N = d_N[s];
    const int nch = d_nch[s], wch0 = d_wch0[s];
    const float* __restrict__ feat = P.feat[s];

    // ---- A geometry: thread = pixel row ----
    const int apix = pix0 + tid;
    const bool aok = (apix < N);
    int ab = 0, ay = 0, ax = 0;
    if (aok) {
        ab = apix / FF;
        int r = apix - ab * FF;
        ay = r / F;
        ax = r - ay * F;
    }
    const float* fb0 = feat + (size_t)ab * C * FF;

    // ---- ldmatrix lane address components ----
    const int a_mloc = (lane & 7) + ((lane >> 3) & 1) * 8;   // 0..15
    const int a_kg   = lane >> 4;                             // 0..1
    const int b_nloc = (lane & 7) + (lane >> 4) * 8;          // 0..15 (x4: two n-tiles)
    const int b_kg   = (lane >> 3) & 1;
    const int b_nloc2 = lane & 7;                             // x2 variant

    float acc[2][19][4];
    #pragma unroll
    for (int mt = 0; mt < 2; mt++)
        #pragma unroll
        for (int nt = 0; nt < 19; nt++)
            #pragma unroll
            for (int q = 0; q < 4; q++) acc[mt][nt][q] = 0.f;

    for (int ch = 0; ch < nch; ch++) {
        __syncthreads();

        // B copy: preprocessed weight image -> smem (hi + lo, 43776 B)
        {
            const uint4* src = (const uint4*)(g_wbf + (size_t)(wch0 + ch) * WCHUNK);
            uint4* dst = (uint4*)(sm + B_HI);
            #pragma unroll 4
            for (int i = tid; i < WCHUNK / 16; i += NTH) dst[i] = src[i];
        }

        // A gather: 64 k-values for this pixel, split hi/lo
        {
            int k0 = ch * 64;
            int kk = k0 >> logC;
            int c0 = k0 & (C - 1);
            int ky = kk / 3, kx = kk - ky * 3;
            int iy = ay + ky - 1, ix = ax + kx - 1;
            bool v = aok && ((unsigned)iy < (unsigned)F) && ((unsigned)ix < (unsigned)F);
            const float* bp = fb0 + (size_t)c0 * FF + iy * F + ix;
            #pragma unroll
            for (int j = 0; j < 64; j += 2) {
                float x0 = v ? __ldg(bp + (size_t)j * FF) : 0.f;
                float x1 = v ? __ldg(bp + (size_t)(j + 1) * FF) : 0.f;
                __nv_bfloat16 h0 = __float2bfloat16(x0);
                __nv_bfloat16 h1 = __float2bfloat16(x1);
                __nv_bfloat16 l0 = __float2bfloat16(x0 - __bfloat162float(h0));
                __nv_bfloat16 l1 = __float2bfloat16(x1 - __bfloat162float(h1));
                uint32_t off = tid * RS + j * 2;
                *(uint32_t*)(sm + A_HI + off) =
                    (uint32_t)__bfloat16_as_ushort(h0) | ((uint32_t)__bfloat16_as_ushort(h1) << 16);
                *(uint32_t*)(sm + A_LO + off) =
                    (uint32_t)__bfloat16_as_ushort(l0) | ((uint32_t)__bfloat16_as_ushort(l1) << 16);
            }
        }
        __syncthreads();

        // compute: 4 k16-steps x (2 m-tiles x 19 n-tiles x 3 terms)
        #pragma unroll
        for (int k16 = 0; k16 < 4; k16++) {
            const uint32_t kgran = (uint32_t)(k16 * 2) * 16;
            uint32_t ah[2][4], al[2][4];
            #pragma unroll
            for (int mt = 0; mt < 2; mt++) {
                uint32_t arow = (uint32_t)(wid * 32 + mt * 16 + a_mloc) * RS + kgran + a_kg * 16;
                ldsm4(ah[mt], smb + A_HI + arow);
                ldsm4(al[mt], smb + A_LO + arow);
            }
            #pragma unroll
            for (int j = 0; j < 18; j += 2) {
                uint32_t brow = (uint32_t)(j * 8 + b_nloc) * RS + kgran + b_kg * 16;
                uint32_t bh[4], bl[4];
                ldsm4(bh, smb + B_HI + brow);
                ldsm4(bl, smb + B_LO + brow);
                #pragma unroll
                for (int mt = 0; mt < 2; mt++) {
                    mma16816(acc[mt][j],     ah[mt], bh);
                    mma16816(acc[mt][j],     ah[mt], bl);
                    mma16816(acc[mt][j],     al[mt], bh);
                    mma16816(acc[mt][j + 1], ah[mt], bh + 2);
                    mma16816(acc[mt][j + 1], ah[mt], bl + 2);
                    mma16816(acc[mt][j + 1], al[mt], bh + 2);
                }
            }
            {   // last n-tile (18), single x2
                uint32_t brow = (uint32_t)(144 + b_nloc2) * RS + kgran + b_kg * 16;
                uint32_t bh[2], bl[2];
                ldsm2(bh, smb + B_HI + brow);
                ldsm2(bl, smb + B_LO + brow);
                #pragma unroll
                for (int mt = 0; mt < 2; mt++) {
                    mma16816(acc[mt][18], ah[mt], bh);
                    mma16816(acc[mt][18], ah[mt], bl);
                    mma16816(acc[mt][18], al[mt], bh);
                }
            }
        }
    }

    __syncthreads();   // all warps done reading A/B smem

    // ---- write accumulators to smem D[128][153] ----
    #pragma unroll
    for (int mt = 0; mt < 2; mt++)
        #pragma unroll
        for (int nt = 0; nt < 19; nt++) {
            int r = wid * 32 + mt * 16 + (lane >> 2);
            int c = nt * 8 + (lane & 3) * 2;
            Dsm[r * 153 + c]           = acc[mt][nt][0];
            Dsm[r * 153 + c + 1]       = acc[mt][nt][1];
            Dsm[(r + 8) * 153 + c]     = acc[mt][nt][2];
            Dsm[(r + 8) * 153 + c + 1] = acc[mt][nt][3];
        }
    __syncthreads();

    // ---- per-pixel bias + decode + softmax ----
    {
        int n = pix0 + tid;
        if (n < N) {
            const float* drow = Dsm + tid * 153;
            int b = n / FF;
            int r = n - b * FF;
            int pbase = d_poff[s] + r * 6;
            float* ob = out + ((size_t)b * NUM_PRIORS + pbase) * 25;
            const float* lb = P.lb[s];
            const float* cb = P.cb[s];
            #pragma unroll
            for (int pic = 0; pic < 6; pic++) {
                const float* pr = priors + (size_t)(pbase + pic) * 4;
                float prx = __ldg(pr + 0), pry = __ldg(pr + 1);
                float prz = __ldg(pr + 2), prw = __ldg(pr + 3);
                float lx = drow[pic * 4 + 0] + __ldg(lb + pic * 4 + 0);
                float ly = drow[pic * 4 + 1] + __ldg(lb + pic * 4 + 1);
                float lw_ = drow[pic * 4 + 2] + __ldg(lb + pic * 4 + 2);
                float lh_ = drow[pic * 4 + 3] + __ldg(lb + pic * 4 + 3);
                float cx = prx + lx * 0.1f * prz;
                float cy = pry + ly * 0.1f * prw;
                float w = prz * expf(lw_ * 0.2f);
                float h = prw * expf(lh_ * 0.2f);
                float mnx = cx - 0.5f * w;
                float mny = cy - 0.5f * h;
                float* o = ob + pic * 25;
                o[0] = mnx; o[1] = mny; o[2] = mnx + w; o[3] = mny + h;

                float vv[21];
                float mx = -1e30f;
                #pragma unroll
                for (int c2 = 0; c2 < 21; c2++) {
                    vv[c2] = drow[24 + pic * 21 + c2] + __ldg(cb + pic * 21 + c2);
                    mx = fmaxf(mx, vv[c2]);
                }
                float ssum = 0.f;
                #pragma unroll
                for (int c2 = 0; c2 < 21; c2++) { vv[c2] = expf(vv[c2] - mx); ssum += vv[c2]; }
                float inv = 1.f / ssum;
                #pragma unroll
                for (int c2 = 0; c2 < 21; c2++) o[4 + c2] = vv[c2] * inv;
            }
        }
    }
}

// ---------------------------------------------------------------------------
extern "C" void kernel_launch(void* const* d_in, const int* in_sizes, int n_in,
                              void* d_out, int out_size)
{
    CParams cp;
    WParams wp;
    const float* priors;

    bool interleaved = (n_in == 31) && (in_sizes[2] == 24);
    if (interleaved) {
        for (int s = 0; s < 6; s++) {
            cp.feat[s] = (const float*)d_in[s * 5 + 0];
            wp.lw[s]   = (const float*)d_in[s * 5 + 1];
            cp.lb[s]   = (const float*)d_in[s * 5 + 2];
            wp.cw[s]   = (const float*)d_in[s * 5 + 3];
            cp.cb[s]   = (const float*)d_in[s * 5 + 4];
        }
        priors = (const float*)d_in[30];
    } else {
        for (int s = 0; s < 6; s++) {
            cp.feat[s] = (const float*)d_in[s];
            wp.lw[s]   = (const float*)d_in[6 + s];
            cp.lb[s]   = (const float*)d_in[12 + s];
            wp.cw[s]   = (const float*)d_in[18 + s];
            cp.cb[s]   = (const float*)d_in[24 + s];
        }
        priors = (const float*)d_in[30];
    }

    cudaFuncSetAttribute(ssd_hmma_kernel,
                         cudaFuncAttributeMaxDynamicSharedMemorySize, SMEM_BYTES);

    prep_weights<<<TOTAL_WCHUNKS, 256>>>(wp);
    ssd_hmma_kernel<<<TOTAL_BLOCKS, NTH, SMEM_BYTES>>>(cp, priors, (float*)d_out);
}

// round 6
// speedup vs baseline: 6.7808x; 1.0351x over previous
#include <cuda_runtime.h>
#include <cuda_bf16.h>
#include <stdint.h>

// ---------------------------------------------------------------------------
// SSD head via warp-level mma.sync (bf16, 3-term hi/lo split), round 6:
// 256-thread blocks (8 warps x 16 pixels x 152 ch), double-buffered smem
// (cp.async B-image copy + software-pipelined A gather), dependency-spaced
// MMA issue order. Epilogue: acc -> smem -> bias + decode + softmax inline.
// ---------------------------------------------------------------------------

#define NUM_PRIORS 11640
#define NTH 256
#define RS 144                         // smem row stride (bytes)
#define WTILE (152 * RS)               // 21888
#define WCHUNK (2 * WTILE)             // 43776 (hi + lo)
#define TOTAL_WCHUNKS 396
#define TOTAL_BLOCKS 488
#define A_HI 0
#define A_LO 18432                     // 128*144
#define B_HI 36864
#define B_LO (36864 + WTILE)           // 58752
#define BUFSZ 80640                    // per-stage buffer
#define SMEM_BYTES (2 * BUFSZ)         // 161280

__device__ __constant__ int d_C[6]    = {512,1024,512,256,256,256};
__device__ __constant__ int d_logC[6] = {9,10,9,8,8,8};
__device__ __constant__ int d_F[6]    = {38,19,10,5,3,1};
__device__ __constant__ int d_FF[6]   = {1444,361,100,25,9,1};
__device__ __constant__ int d_N[6]    = {46208,11552,3200,800,288,32};
__device__ __constant__ int d_nch[6]  = {72,144,72,36,36,36};
__device__ __constant__ int d_wch0[6] = {0,72,216,288,324,360};
__device__ __constant__ int d_poff[6] = {0,8664,10830,11430,11580,11634};
__device__ __constant__ int d_bstart[7] = {0,91,452,477,484,487,488};
__device__ __constant__ int d_border[6] = {1,0,2,3,4,5};

__device__ unsigned char g_wbf[(size_t)TOTAL_WCHUNKS * WCHUNK];

struct WParams { const float* lw[6]; const float* cw[6]; };
struct CParams { const float* feat[6]; const float* lb[6]; const float* cb[6]; };

// ---- PTX helpers ------------------------------------------------------------
__device__ __forceinline__ uint32_t smaddr(const void* p) {
    return (uint32_t)__cvta_generic_to_shared(p);
}
__device__ __forceinline__ void ldsm4(uint32_t* r, uint32_t a) {
    asm volatile("ldmatrix.sync.aligned.m8n8.x4.shared.b16 {%0,%1,%2,%3}, [%4];"
                 : "=r"(r[0]), "=r"(r[1]), "=r"(r[2]), "=r"(r[3]) : "r"(a));
}
__device__ __forceinline__ void ldsm2(uint32_t* r, uint32_t a) {
    asm volatile("ldmatrix.sync.aligned.m8n8.x2.shared.b16 {%0,%1}, [%2];"
                 : "=r"(r[0]), "=r"(r[1]) : "r"(a));
}
__device__ __forceinline__ void mma16816(float* d, const uint32_t* a, const uint32_t* b) {
    asm volatile("mma.sync.aligned.m16n8k16.row.col.f32.bf16.bf16.f32 "
                 "{%0,%1,%2,%3},{%4,%5,%6,%7},{%8,%9},{%0,%1,%2,%3};"
                 : "+f"(d[0]), "+f"(d[1]), "+f"(d[2]), "+f"(d[3])
                 : "r"(a[0]), "r"(a[1]), "r"(a[2]), "r"(a[3]),
                   "r"(b[0]), "r"(b[1]));
}
__device__ __forceinline__ void cpasync16(uint32_t dst, const void* src) {
    asm volatile("cp.async.cg.shared.global [%0], [%1], 16;"
                 :: "r"(dst), "l"(src) : "memory");
}
__device__ __forceinline__ void cpcommit() {
    asm volatile("cp.async.commit_group;" ::: "memory");
}
__device__ __forceinline__ void cpwait0() {
    asm volatile("cp.async.wait_group 0;" ::: "memory");
}

// ---- weight preprocessing: split bf16 hi/lo, kk-major, 144B row stride ------
__global__ __launch_bounds__(256) void prep_weights(WParams P)
{
    int ch = blockIdx.x;
    int s = 0;
    #pragma unroll
    for (int i = 1; i < 6; i++) if (ch >= d_wch0[i]) s = i;
    int cis = ch - d_wch0[s];
    int C = d_C[s];
    int K = C * 9;
    int k0 = cis * 64;
    int kk = k0 >> d_logC[s];
    int c0 = k0 & (C - 1);
    size_t base = (size_t)ch * WCHUNK;

    for (int e = threadIdx.x; e < 152 * 64; e += blockDim.x) {
        int row = e >> 6;
        int col = e & 63;
        float v = 0.f;
        if (row < 150) {
            int widx = (c0 + col) * 9 + kk;
            v = (row < 24) ? P.lw[s][(size_t)row * K + widx]
                           : P.cw[s][(size_t)(row - 24) * K + widx];
        }
        __nv_bfloat16 h = __float2bfloat16(v);
        __nv_bfloat16 l = __float2bfloat16(v - __bfloat162float(h));
        size_t off = base + (size_t)row * RS + col * 2;
        *(__nv_bfloat16*)(g_wbf + off) = h;
        *(__nv_bfloat16*)(g_wbf + off + WTILE) = l;
    }
}

// ---- main fused kernel --------------------------------------------------------
__global__ __launch_bounds__(NTH, 1) void ssd_hmma_kernel(
    CParams P, const float* __restrict__ priors, float* __restrict__ out)
{
    extern __shared__ __align__(16) unsigned char sm[];
    float* Dsm = (float*)sm;
    const uint32_t smb = smaddr(sm);

    const int tid = threadIdx.x;
    const int wid = tid >> 5;
    const int lane = tid & 31;

    // ---- block -> (stage, pixel tile) ----
    int bid = blockIdx.x;
    int oi = 0;
    #pragma unroll
    for (int i = 1; i < 6; i++) if (bid >= d_bstart[i]) oi = i;
    const int s = d_border[oi];
    const int pix0 = (bid - d_bstart[oi]) * 128;

    const int C = d_C[s], logC = d_logC[s], F = d_F[s], FF = d_FF[s], N = d_N[s];
    const int nch = d_nch[s], wch0 = d_wch0[s];
    const float* __restrict__ feat = P.feat[s];

    // ---- A gather geometry: 2 threads per pixel row, 32 k-values each ----
    const int arow = tid >> 1;              // 0..127
    const int ahalf = (tid & 1) * 32;       // k offset within 64-chunk
    const int apix = pix0 + arow;
    const bool aok = (apix < N);
    int ab = 0, ay = 0, ax = 0;
    if (aok) {
        ab = apix / FF;
        int r = apix - ab * FF;
        ay = r / F;
        ax = r - ay * F;
    }
    const float* fb0 = feat + (size_t)ab * C * FF;

    // ---- ldmatrix lane address components ----
    const int a_mloc = (lane & 7) + ((lane >> 3) & 1) * 8;   // 0..15
    const int a_kg   = lane >> 4;                             // 0..1
    const int b_nloc = (lane & 7) + (lane >> 4) * 8;          // x4 (two n-tiles)
    const int b_kg   = (lane >> 3) & 1;
    const int b_nloc2 = lane & 7;                             // x2 variant

    float acc[19][4];
    #pragma unroll
    for (int nt = 0; nt < 19; nt++)
        #pragma unroll
        for (int q = 0; q < 4; q++) acc[nt][q] = 0.f;

    // ---------------- helpers (inline lambdas) ----------------
    auto copyB = [&](int ch, int buf) {
        const uint4* src = (const uint4*)(g_wbf + (size_t)(wch0 + ch) * WCHUNK);
        uint32_t dst = smb + buf * BUFSZ + B_HI;
        #pragma unroll 3
        for (int i = tid; i < WCHUNK / 16; i += NTH)
            cpasync16(dst + i * 16, src + i);
    };
    float xg[32];
    auto gatherA = [&](int ch) {
        int k0 = ch * 64;
        int kk = k0 >> logC;
        int c0 = k0 & (C - 1);
        int ky = kk / 3, kx = kk - ky * 3;
        int iy = ay + ky - 1, ix = ax + kx - 1;
        bool v = aok && ((unsigned)iy < (unsigned)F) && ((unsigned)ix < (unsigned)F);
        const float* bp = fb0 + (size_t)(c0 + ahalf) * FF + iy * F + ix;
        #pragma unroll
        for (int j = 0; j < 32; j++)
            xg[j] = v ? __ldg(bp + (size_t)j * FF) : 0.f;
    };
    auto storeA = [&](int buf) {
        unsigned char* b = sm + buf * BUFSZ;
        #pragma unroll
        for (int j = 0; j < 32; j += 2) {
            __nv_bfloat16 h0 = __float2bfloat16(xg[j]);
            __nv_bfloat16 h1 = __float2bfloat16(xg[j + 1]);
            __nv_bfloat16 l0 = __float2bfloat16(xg[j] - __bfloat162float(h0));
            __nv_bfloat16 l1 = __float2bfloat16(xg[j + 1] - __bfloat162float(h1));
            uint32_t off = arow * RS + (ahalf + j) * 2;
            *(uint32_t*)(b + A_HI + off) =
                (uint32_t)__bfloat16_as_ushort(h0) | ((uint32_t)__bfloat16_as_ushort(h1) << 16);
            *(uint32_t*)(b + A_LO + off) =
                (uint32_t)__bfloat16_as_ushort(l0) | ((uint32_t)__bfloat16_as_ushort(l1) << 16);
        }
    };
    auto compute = [&](int buf) {
        const uint32_t ba = smb + buf * BUFSZ;
        #pragma unroll
        for (int k16 = 0; k16 < 4; k16++) {
            const uint32_t kgran = (uint32_t)k16 * 32;
            uint32_t ah[4], al[4];
            uint32_t arow_a = (uint32_t)(wid * 16 + a_mloc) * RS + kgran + a_kg * 16;
            ldsm4(ah, ba + A_HI + arow_a);
            ldsm4(al, ba + A_LO + arow_a);
            #pragma unroll
            for (int g = 0; g < 4; g++) {           // n-tiles 4g .. 4g+3
                int j = g * 4;
                uint32_t bh[8], bl[8];
                uint32_t br0 = (uint32_t)(j * 8 + b_nloc) * RS + kgran + b_kg * 16;
                uint32_t br1 = (uint32_t)((j + 2) * 8 + b_nloc) * RS + kgran + b_kg * 16;
                ldsm4(bh,     ba + B_HI + br0);
                ldsm4(bh + 4, ba + B_HI + br1);
                ldsm4(bl,     ba + B_LO + br0);
                ldsm4(bl + 4, ba + B_LO + br1);
                // spacing-4 issue order: hh x4, hl x4, lh x4
                mma16816(acc[j],     ah, bh);
                mma16816(acc[j + 1], ah, bh + 2);
                mma16816(acc[j + 2], ah, bh + 4);
                mma16816(acc[j + 3], ah, bh + 6);
                mma16816(acc[j],     ah, bl);
                mma16816(acc[j + 1], ah, bl + 2);
                mma16816(acc[j + 2], ah, bl + 4);
                mma16816(acc[j + 3], ah, bl + 6);
                mma16816(acc[j],     al, bh);
                mma16816(acc[j + 1], al, bh + 2);
                mma16816(acc[j + 2], al, bh + 4);
                mma16816(acc[j + 3], al, bh + 6);
            }
            {   // tail: n-tiles 16,17 (x4) + 18 (x2)
                uint32_t bh[6], bl[6];
                uint32_t br0 = (uint32_t)(128 + b_nloc) * RS + kgran + b_kg * 16;
                uint32_t br2 = (uint32_t)(144 + b_nloc2) * RS + kgran + b_kg * 16;
                ldsm4(bh, ba + B_HI + br0);
                ldsm2(bh + 4, ba + B_HI + br2);
                ldsm4(bl, ba + B_LO + br0);
                ldsm2(bl + 4, ba + B_LO + br2);
                mma16816(acc[16], ah, bh);
                mma16816(acc[17], ah, bh + 2);
                mma16816(acc[18], ah, bh + 4);
                mma16816(acc[16], ah, bl);
                mma16816(acc[17], ah, bl + 2);
                mma16816(acc[18], ah, bl + 4);
                mma16816(acc[16], al, bh);
                mma16816(acc[17], al, bh + 2);
                mma16816(acc[18], al, bh + 4);
            }
        }
    };

    // ---------------- pipeline ----------------
    copyB(0, 0);
    cpcommit();
    gatherA(0);
    storeA(0);
    cpwait0();
    __syncthreads();

    for (int ch = 0; ch < nch; ch++) {
        int cur = ch & 1;
        bool pf = (ch + 1 < nch);
        if (pf) {
            copyB(ch + 1, cur ^ 1);
            cpcommit();
            gatherA(ch + 1);        // LDGs in flight during MMAs
        }
        compute(cur);
        if (pf) storeA(cur ^ 1);    // convert + STS after MMAs
        cpwait0();
        __syncthreads();
    }

    // ---- write accumulators to smem D[128][153] (buf0 region is free) ----
    #pragma unroll
    for (int nt = 0; nt < 19; nt++) {
        int r = wid * 16 + (lane >> 2);
        int c = nt * 8 + (lane & 3) * 2;
        Dsm[r * 153 + c]           = acc[nt][0];
        Dsm[r * 153 + c + 1]       = acc[nt][1];
        Dsm[(r + 8) * 153 + c]     = acc[nt][2];
        Dsm[(r + 8) * 153 + c + 1] = acc[nt][3];
    }
    __syncthreads();

    // ---- per-pixel bias + decode + softmax ----
    if (tid < 128) {
        int n = pix0 + tid;
        if (n < N) {
            const float* drow = Dsm + tid * 153;
            int b = n / FF;
            int r = n - b * FF;
            int pbase = d_poff[s] + r * 6;
            float* ob = out + ((size_t)b * NUM_PRIORS + pbase) * 25;
            const float* lb = P.lb[s];
            const float* cb = P.cb[s];
            #pragma unroll
            for (int pic = 0; pic < 6; pic++) {
                const float* pr = priors + (size_t)(pbase + pic) * 4;
                float prx = __ldg(pr + 0), pry = __ldg(pr + 1);
                float prz = __ldg(pr + 2), prw = __ldg(pr + 3);
                float lx = drow[pic * 4 + 0] + __ldg(lb + pic * 4 + 0);
                float ly = drow[pic * 4 + 1] + __ldg(lb + pic * 4 + 1);
                float lw_ = drow[pic * 4 + 2] + __ldg(lb + pic * 4 + 2);
                float lh_ = drow[pic * 4 + 3] + __ldg(lb + pic * 4 + 3);
                float cx = prx + lx * 0.1f * prz;
                float cy = pry + ly * 0.1f * prw;
                float w = prz * expf(lw_ * 0.2f);
                float h = prw * expf(lh_ * 0.2f);
                float mnx = cx - 0.5f * w;
                float mny = cy - 0.5f * h;
                float* o = ob + pic * 25;
                o[0] = mnx; o[1] = mny; o[2] = mnx + w; o[3] = mny + h;

                float vv[21];
                float mx = -1e30f;
                #pragma unroll
                for (int c2 = 0; c2 < 21; c2++) {
                    vv[c2] = drow[24 + pic * 21 + c2] + __ldg(cb + pic * 21 + c2);
                    mx = fmaxf(mx, vv[c2]);
                }
                float ssum = 0.f;
                #pragma unroll
                for (int c2 = 0; c2 < 21; c2++) { vv[c2] = expf(vv[c2] - mx); ssum += vv[c2]; }
                float inv = 1.f / ssum;
                #pragma unroll
                for (int c2 = 0; c2 < 21; c2++) o[4 + c2] = vv[c2] * inv;
            }
        }
    }
}

// ---------------------------------------------------------------------------
extern "C" void kernel_launch(void* const* d_in, const int* in_sizes, int n_in,
                              void* d_out, int out_size)
{
    CParams cp;
    WParams wp;
    const float* priors;

    bool interleaved = (n_in == 31) && (in_sizes[2] == 24);
    if (interleaved) {
        for (int s = 0; s < 6; s++) {
            cp.feat[s] = (const float*)d_in[s * 5 + 0];
            wp.lw[s]   = (const float*)d_in[s * 5 + 1];
            cp.lb[s]   = (const float*)d_in[s * 5 + 2];
            wp.cw[s]   = (const float*)d_in[s * 5 + 3];
            cp.cb[s]   = (const float*)d_in[s * 5 + 4];
        }
        priors = (const float*)d_in[30];
    } else {
        for (int s = 0; s < 6; s++) {
            cp.feat[s] = (const float*)d_in[s];
            wp.lw[s]   = (const float*)d_in[6 + s];
            cp.lb[s]   = (const float*)d_in[12 + s];
            wp.cw[s]   = (const float*)d_in[18 + s];
            cp.cb[s]   = (const float*)d_in[24 + s];
        }
        priors = (const float*)d_in[30];
    }

    cudaFuncSetAttribute(ssd_hmma_kernel,
                         cudaFuncAttributeMaxDynamicSharedMemorySize, SMEM_BYTES);

    prep_weights<<<TOTAL_WCHUNKS, 256>>>(wp);
    ssd_hmma_kernel<<<TOTAL_BLOCKS, NTH, SMEM_BYTES>>>(cp, priors, (float*)d_out);
}

// round 7
// speedup vs baseline: 6.8599x; 1.0117x over previous
#include <cuda_runtime.h>
#include <cuda_bf16.h>
#include <stdint.h>

// ---------------------------------------------------------------------------
// SSD head via warp-level mma.sync (bf16, 3-term hi/lo split), round 7:
// N-split warp specialization: warps 0-3 -> n-tiles 0..9, warps 4-7 ->
// n-tiles 10..18; each warp owns 32 pixels (2 m-tiles). Halves B-fragment
// LDSM traffic per MMA and doubles independent accumulators per fragment.
// Double-buffered smem (cp.async B copy + pipelined A gather) as before.
// ---------------------------------------------------------------------------

#define NUM_PRIORS 11640
#define NTH 256
#define RS 144                         // smem row stride (bytes)
#define WTILE (152 * RS)               // 21888
#define WCHUNK (2 * WTILE)             // 43776 (hi + lo)
#define TOTAL_WCHUNKS 396
#define TOTAL_BLOCKS 488
#define A_HI 0
#define A_LO 18432                     // 128*144
#define B_HI 36864
#define B_LO (36864 + WTILE)           // 58752
#define BUFSZ 80640
#define SMEM_BYTES (2 * BUFSZ)         // 161280

__device__ __constant__ int d_C[6]    = {512,1024,512,256,256,256};
__device__ __constant__ int d_logC[6] = {9,10,9,8,8,8};
__device__ __constant__ int d_F[6]    = {38,19,10,5,3,1};
__device__ __constant__ int d_FF[6]   = {1444,361,100,25,9,1};
__device__ __constant__ int d_N[6]    = {46208,11552,3200,800,288,32};
__device__ __constant__ int d_nch[6]  = {72,144,72,36,36,36};
__device__ __constant__ int d_wch0[6] = {0,72,216,288,324,360};
__device__ __constant__ int d_poff[6] = {0,8664,10830,11430,11580,11634};
__device__ __constant__ int d_bstart[7] = {0,91,452,477,484,487,488};
__device__ __constant__ int d_border[6] = {1,0,2,3,4,5};

__device__ unsigned char g_wbf[(size_t)TOTAL_WCHUNKS * WCHUNK];

struct WParams { const float* lw[6]; const float* cw[6]; };
struct CParams { const float* feat[6]; const float* lb[6]; const float* cb[6]; };

// ---- PTX helpers ------------------------------------------------------------
__device__ __forceinline__ uint32_t smaddr(const void* p) {
    return (uint32_t)__cvta_generic_to_shared(p);
}
__device__ __forceinline__ void ldsm4(uint32_t* r, uint32_t a) {
    asm volatile("ldmatrix.sync.aligned.m8n8.x4.shared.b16 {%0,%1,%2,%3}, [%4];"
                 : "=r"(r[0]), "=r"(r[1]), "=r"(r[2]), "=r"(r[3]) : "r"(a));
}
__device__ __forceinline__ void ldsm2(uint32_t* r, uint32_t a) {
    asm volatile("ldmatrix.sync.aligned.m8n8.x2.shared.b16 {%0,%1}, [%2];"
                 : "=r"(r[0]), "=r"(r[1]) : "r"(a));
}
__device__ __forceinline__ void mma16816(float* d, const uint32_t* a, const uint32_t* b) {
    asm volatile("mma.sync.aligned.m16n8k16.row.col.f32.bf16.bf16.f32 "
                 "{%0,%1,%2,%3},{%4,%5,%6,%7},{%8,%9},{%0,%1,%2,%3};"
                 : "+f"(d[0]), "+f"(d[1]), "+f"(d[2]), "+f"(d[3])
                 : "r"(a[0]), "r"(a[1]), "r"(a[2]), "r"(a[3]),
                   "r"(b[0]), "r"(b[1]));
}
__device__ __forceinline__ void cpasync16(uint32_t dst, const void* src) {
    asm volatile("cp.async.cg.shared.global [%0], [%1], 16;"
                 :: "r"(dst), "l"(src) : "memory");
}
__device__ __forceinline__ void cpcommit() {
    asm volatile("cp.async.commit_group;" ::: "memory");
}
__device__ __forceinline__ void cpwait0() {
    asm volatile("cp.async.wait_group 0;" ::: "memory");
}

// ---- weight preprocessing: split bf16 hi/lo, kk-major, 144B row stride ------
__global__ __launch_bounds__(256) void prep_weights(WParams P)
{
    int ch = blockIdx.x;
    int s = 0;
    #pragma unroll
    for (int i = 1; i < 6; i++) if (ch >= d_wch0[i]) s = i;
    int cis = ch - d_wch0[s];
    int C = d_C[s];
    int K = C * 9;
    int k0 = cis * 64;
    int kk = k0 >> d_logC[s];
    int c0 = k0 & (C - 1);
    size_t base = (size_t)ch * WCHUNK;

    for (int e = threadIdx.x; e < 152 * 64; e += blockDim.x) {
        int row = e >> 6;
        int col = e & 63;
        float v = 0.f;
        if (row < 150) {
            int widx = (c0 + col) * 9 + kk;
            v = (row < 24) ? P.lw[s][(size_t)row * K + widx]
                           : P.cw[s][(size_t)(row - 24) * K + widx];
        }
        __nv_bfloat16 h = __float2bfloat16(v);
        __nv_bfloat16 l = __float2bfloat16(v - __bfloat162float(h));
        size_t off = base + (size_t)row * RS + col * 2;
        *(__nv_bfloat16*)(g_wbf + off) = h;
        *(__nv_bfloat16*)(g_wbf + off + WTILE) = l;
    }
}

// ---- main fused kernel --------------------------------------------------------
__global__ __launch_bounds__(NTH, 1) void ssd_hmma_kernel(
    CParams P, const float* __restrict__ priors, float* __restrict__ out)
{
    extern __shared__ __align__(16) unsigned char sm[];
    float* Dsm = (float*)sm;
    const uint32_t smb = smaddr(sm);

    const int tid = threadIdx.x;
    const int wid = tid >> 5;
    const int lane = tid & 31;
    const int grp = wid >> 2;             // 0: n-tiles 0..9, 1: n-tiles 10..18
    const int mrow0 = (wid & 3) * 32;     // 32 pixels per warp (2 m-tiles)

    // ---- block -> (stage, pixel tile) ----
    int bid = blockIdx.x;
    int oi = 0;
    #pragma unroll
    for (int i = 1; i < 6; i++) if (bid >= d_bstart[i]) oi = i;
    const int s = d_border[oi];
    const int pix0 = (bid - d_bstart[oi]) * 128;

    const int C = d_C[s], logC = d_logC[s], F = d_F[s], FF = d_FF[s], N = d_N[s];
    const int nch = d_nch[s], wch0 = d_wch0[s];
    const float* __restrict__ feat = P.feat[s];

    // ---- A gather geometry: 2 threads per pixel row, 32 k-values each ----
    const int arow = tid >> 1;
    const int ahalf = (tid & 1) * 32;
    const int apix = pix0 + arow;
    const bool aok = (apix < N);
    int ab = 0, ay = 0, ax = 0;
    if (aok) {
        ab = apix / FF;
        int r = apix - ab * FF;
        ay = r / F;
        ax = r - ay * F;
    }
    const float* fb0 = feat + (size_t)ab * C * FF;

    // ---- ldmatrix lane address components ----
    const int a_mloc = (lane & 7) + ((lane >> 3) & 1) * 8;
    const int a_kg   = lane >> 4;
    const int b_nloc = (lane & 7) + (lane >> 4) * 8;
    const int b_kg   = (lane >> 3) & 1;
    const int b_nloc2 = lane & 7;

    float acc[2][10][4];
    #pragma unroll
    for (int mt = 0; mt < 2; mt++)
        #pragma unroll
        for (int nt = 0; nt < 10; nt++)
            #pragma unroll
            for (int q = 0; q < 4; q++) acc[mt][nt][q] = 0.f;

    // ---------------- helpers ----------------
    auto copyB = [&](int ch, int buf) {
        const uint4* src = (const uint4*)(g_wbf + (size_t)(wch0 + ch) * WCHUNK);
        uint32_t dst = smb + buf * BUFSZ + B_HI;
        #pragma unroll 3
        for (int i = tid; i < WCHUNK / 16; i += NTH)
            cpasync16(dst + i * 16, src + i);
    };
    float xg[32];
    auto gatherA = [&](int ch) {
        int k0 = ch * 64;
        int kk = k0 >> logC;
        int c0 = k0 & (C - 1);
        int ky = kk / 3, kx = kk - ky * 3;
        int iy = ay + ky - 1, ix = ax + kx - 1;
        bool v = aok && ((unsigned)iy < (unsigned)F) && ((unsigned)ix < (unsigned)F);
        const float* bp = fb0 + (size_t)(c0 + ahalf) * FF + iy * F + ix;
        #pragma unroll
        for (int j = 0; j < 32; j++)
            xg[j] = v ? __ldg(bp + (size_t)j * FF) : 0.f;
    };
    auto storeA = [&](int buf) {
        unsigned char* b = sm + buf * BUFSZ;
        #pragma unroll
        for (int j = 0; j < 32; j += 2) {
            __nv_bfloat16 h0 = __float2bfloat16(xg[j]);
            __nv_bfloat16 h1 = __float2bfloat16(xg[j + 1]);
            __nv_bfloat16 l0 = __float2bfloat16(xg[j] - __bfloat162float(h0));
            __nv_bfloat16 l1 = __float2bfloat16(xg[j + 1] - __bfloat162float(h1));
            uint32_t off = arow * RS + (ahalf + j) * 2;
            *(uint32_t*)(b + A_HI + off) =
                (uint32_t)__bfloat16_as_ushort(h0) | ((uint32_t)__bfloat16_as_ushort(h1) << 16);
            *(uint32_t*)(b + A_LO + off) =
                (uint32_t)__bfloat16_as_ushort(l0) | ((uint32_t)__bfloat16_as_ushort(l1) << 16);
        }
    };
    auto compute = [&](int buf) {
        const uint32_t ba = smb + buf * BUFSZ;
        #pragma unroll
        for (int k16 = 0; k16 < 4; k16++) {
            const uint32_t kgran = (uint32_t)k16 * 32;
            uint32_t ah[2][4], al[2][4];
            #pragma unroll
            for (int mt = 0; mt < 2; mt++) {
                uint32_t ra = (uint32_t)(mrow0 + mt * 16 + a_mloc) * RS + kgran + a_kg * 16;
                ldsm4(ah[mt], ba + A_HI + ra);
                ldsm4(al[mt], ba + A_LO + ra);
            }
            if (grp == 0) {
                #pragma unroll
                for (int g = 0; g < 5; g++) {     // n-tiles 2g, 2g+1
                    int j = g * 2;
                    uint32_t bh[4], bl[4];
                    uint32_t br = (uint32_t)(j * 8 + b_nloc) * RS + kgran + b_kg * 16;
                    ldsm4(bh, ba + B_HI + br);
                    ldsm4(bl, ba + B_LO + br);
                    mma16816(acc[0][j],     ah[0], bh);
                    mma16816(acc[1][j],     ah[1], bh);
                    mma16816(acc[0][j + 1], ah[0], bh + 2);
                    mma16816(acc[1][j + 1], ah[1], bh + 2);
                    mma16816(acc[0][j],     ah[0], bl);
                    mma16816(acc[1][j],     ah[1], bl);
                    mma16816(acc[0][j + 1], ah[0], bl + 2);
                    mma16816(acc[1][j + 1], ah[1], bl + 2);
                    mma16816(acc[0][j],     al[0], bh);
                    mma16816(acc[1][j],     al[1], bh);
                    mma16816(acc[0][j + 1], al[0], bh + 2);
                    mma16816(acc[1][j + 1], al[1], bh + 2);
                }
            } else {
                #pragma unroll
                for (int g = 0; g < 4; g++) {     // global n-tiles 10+2g, 11+2g
                    int j = g * 2;
                    uint32_t bh[4], bl[4];
                    uint32_t br = (uint32_t)(80 + j * 8 + b_nloc) * RS + kgran + b_kg * 16;
                    ldsm4(bh, ba + B_HI + br);
                    ldsm4(bl, ba + B_LO + br);
                    mma16816(acc[0][j],     ah[0], bh);
                    mma16816(acc[1][j],     ah[1], bh);
                    mma16816(acc[0][j + 1], ah[0], bh + 2);
                    mma16816(acc[1][j + 1], ah[1], bh + 2);
                    mma16816(acc[0][j],     ah[0], bl);
                    mma16816(acc[1][j],     ah[1], bl);
                    mma16816(acc[0][j + 1], ah[0], bl + 2);
                    mma16816(acc[1][j + 1], ah[1], bl + 2);
                    mma16816(acc[0][j],     al[0], bh);
                    mma16816(acc[1][j],     al[1], bh);
                    mma16816(acc[0][j + 1], al[0], bh + 2);
                    mma16816(acc[1][j + 1], al[1], bh + 2);
                }
                {   // global n-tile 18 (local 8), x2
                    uint32_t bh[2], bl[2];
                    uint32_t br = (uint32_t)(144 + b_nloc2) * RS + kgran + b_kg * 16;
                    ldsm2(bh, ba + B_HI + br);
                    ldsm2(bl, ba + B_LO + br);
                    mma16816(acc[0][8], ah[0], bh);
                    mma16816(acc[1][8], ah[1], bh);
                    mma16816(acc[0][8], ah[0], bl);
                    mma16816(acc[1][8], ah[1], bl);
                    mma16816(acc[0][8], al[0], bh);
                    mma16816(acc[1][8], al[1], bh);
                }
            }
        }
    };

    // ---------------- pipeline ----------------
    copyB(0, 0);
    cpcommit();
    gatherA(0);
    storeA(0);
    cpwait0();
    __syncthreads();

    for (int ch = 0; ch < nch; ch++) {
        int cur = ch & 1;
        bool pf = (ch + 1 < nch);
        if (pf) {
            copyB(ch + 1, cur ^ 1);
            cpcommit();
            gatherA(ch + 1);
        }
        compute(cur);
        if (pf) storeA(cur ^ 1);
        cpwait0();
        __syncthreads();
    }

    // ---- write accumulators to smem D[128][153] ----
    {
        const int ntl = grp ? 9 : 10;
        const int colb = grp ? 80 : 0;
        #pragma unroll
        for (int mt = 0; mt < 2; mt++)
            for (int nt = 0; nt < ntl; nt++) {
                int r = mrow0 + mt * 16 + (lane >> 2);
                int c = colb + nt * 8 + (lane & 3) * 2;
                Dsm[r * 153 + c]           = acc[mt][nt][0];
                Dsm[r * 153 + c + 1]       = acc[mt][nt][1];
                Dsm[(r + 8) * 153 + c]     = acc[mt][nt][2];
                Dsm[(r + 8) * 153 + c + 1] = acc[mt][nt][3];
            }
    }
    __syncthreads();

    // ---- per-pixel bias + decode + softmax ----
    if (tid < 128) {
        int n = pix0 + tid;
        if (n < N) {
            const float* drow = Dsm + tid * 153;
            int b = n / FF;
            int r = n - b * FF;
            int pbase = d_poff[s] + r * 6;
            float* ob = out + ((size_t)b * NUM_PRIORS + pbase) * 25;
            const float* lb = P.lb[s];
            const float* cb = P.cb[s];
            #pragma unroll
            for (int pic = 0; pic < 6; pic++) {
                const float* pr = priors + (size_t)(pbase + pic) * 4;
                float prx = __ldg(pr + 0), pry = __ldg(pr + 1);
                float prz = __ldg(pr + 2), prw = __ldg(pr + 3);
                float lx = drow[pic * 4 + 0] + __ldg(lb + pic * 4 + 0);
                float ly = drow[pic * 4 + 1] + __ldg(lb + pic * 4 + 1);
                float lw_ = drow[pic * 4 + 2] + __ldg(lb + pic * 4 + 2);
                float lh_ = drow[pic * 4 + 3] + __ldg(lb + pic * 4 + 3);
                float cx = prx + lx * 0.1f * prz;
                float cy = pry + ly * 0.1f * prw;
                float w = prz * expf(lw_ * 0.2f);
                float h = prw * expf(lh_ * 0.2f);
                float mnx = cx - 0.5f * w;
                float mny = cy - 0.5f * h;
                float* o = ob + pic * 25;
                o[0] = mnx; o[1] = mny; o[2] = mnx + w; o[3] = mny + h;

                float vv[21];
                float mx = -1e30f;
                #pragma unroll
                for (int c2 = 0; c2 < 21; c2++) {
                    vv[c2] = drow[24 + pic * 21 + c2] + __ldg(cb + pic * 21 + c2);
                    mx = fmaxf(mx, vv[c2]);
                }
                float ssum = 0.f;
                #pragma unroll
                for (int c2 = 0; c2 < 21; c2++) { vv[c2] = expf(vv[c2] - mx); ssum += vv[c2]; }
                float inv = 1.f / ssum;
                #pragma unroll
                for (int c2 = 0; c2 < 21; c2++) o[4 + c2] = vv[c2] * inv;
            }
        }
    }
}

// ---------------------------------------------------------------------------
extern "C" void kernel_launch(void* const* d_in, const int* in_sizes, int n_in,
                              void* d_out, int out_size)
{
    CParams cp;
    WParams wp;
    const float* priors;

    bool interleaved = (n_in == 31) && (in_sizes[2] == 24);
    if (interleaved) {
        for (int s = 0; s < 6; s++) {
            cp.feat[s] = (const float*)d_in[s * 5 + 0];
            wp.lw[s]   = (const float*)d_in[s * 5 + 1];
            cp.lb[s]   = (const float*)d_in[s * 5 + 2];
            wp.cw[s]   = (const float*)d_in[s * 5 + 3];
            cp.cb[s]   = (const float*)d_in[s * 5 + 4];
        }
        priors = (const float*)d_in[30];
    } else {
        for (int s = 0; s < 6; s++) {
            cp.feat[s] = (const float*)d_in[s];
            wp.lw[s]   = (const float*)d_in[6 + s];
            cp.lb[s]   = (const float*)d_in[12 + s];
            wp.cw[s]   = (const float*)d_in[18 + s];
            cp.cb[s]   = (const float*)d_in[24 + s];
        }
        priors = (const float*)d_in[30];
    }

    cudaFuncSetAttribute(ssd_hmma_kernel,
                         cudaFuncAttributeMaxDynamicSharedMemorySize, SMEM_BYTES);

    prep_weights<<<TOTAL_WCHUNKS, 256>>>(wp);
    ssd_hmma_kernel<<<TOTAL_BLOCKS, NTH, SMEM_BYTES>>>(cp, priors, (float*)d_out);
}

// round 8
// speedup vs baseline: 6.8728x; 1.0019x over previous
#include <cuda_runtime.h>
#include <cuda_bf16.h>
#include <stdint.h>

// ---------------------------------------------------------------------------
// SSD head via warp-level mma.sync (bf16, 3-term hi/lo split), round 8:
// 512 threads / 16 warps per CTA (4 per SMSP) to cover MMA/LDSM latency.
// Warp (wid&7) -> m-tile (16 pixels), (wid>>3) -> n-group (tiles 0-9 / 10-18).
// Double-buffered smem (cp.async B copy + pipelined 4-thread/pixel A gather).
// Epilogue: acc -> smem -> bias + box decode + softmax inline.
// ---------------------------------------------------------------------------

#define NUM_PRIORS 11640
#define NTH 512
#define RS 144                         // smem row stride (bytes)
#define WTILE (152 * RS)               // 21888
#define WCHUNK (2 * WTILE)             // 43776 (hi + lo)
#define TOTAL_WCHUNKS 396
#define TOTAL_BLOCKS 488
#define A_HI 0
#define A_LO 18432                     // 128*144
#define B_HI 36864
#define B_LO (36864 + WTILE)           // 58752
#define BUFSZ 80640
#define SMEM_BYTES (2 * BUFSZ)         // 161280

__device__ __constant__ int d_C[6]    = {512,1024,512,256,256,256};
__device__ __constant__ int d_logC[6] = {9,10,9,8,8,8};
__device__ __constant__ int d_F[6]    = {38,19,10,5,3,1};
__device__ __constant__ int d_FF[6]   = {1444,361,100,25,9,1};
__device__ __constant__ int d_N[6]    = {46208,11552,3200,800,288,32};
__device__ __constant__ int d_nch[6]  = {72,144,72,36,36,36};
__device__ __constant__ int d_wch0[6] = {0,72,216,288,324,360};
__device__ __constant__ int d_poff[6] = {0,8664,10830,11430,11580,11634};
__device__ __constant__ int d_bstart[7] = {0,91,452,477,484,487,488};
__device__ __constant__ int d_border[6] = {1,0,2,3,4,5};

__device__ unsigned char g_wbf[(size_t)TOTAL_WCHUNKS * WCHUNK];

struct WParams { const float* lw[6]; const float* cw[6]; };
struct CParams { const float* feat[6]; const float* lb[6]; const float* cb[6]; };

// ---- PTX helpers ------------------------------------------------------------
__device__ __forceinline__ uint32_t smaddr(const void* p) {
    return (uint32_t)__cvta_generic_to_shared(p);
}
__device__ __forceinline__ void ldsm4(uint32_t* r, uint32_t a) {
    asm volatile("ldmatrix.sync.aligned.m8n8.x4.shared.b16 {%0,%1,%2,%3}, [%4];"
                 : "=r"(r[0]), "=r"(r[1]), "=r"(r[2]), "=r"(r[3]) : "r"(a));
}
__device__ __forceinline__ void ldsm2(uint32_t* r, uint32_t a) {
    asm volatile("ldmatrix.sync.aligned.m8n8.x2.shared.b16 {%0,%1}, [%2];"
                 : "=r"(r[0]), "=r"(r[1]) : "r"(a));
}
__device__ __forceinline__ void mma16816(float* d, const uint32_t* a, const uint32_t* b) {
    asm volatile("mma.sync.aligned.m16n8k16.row.col.f32.bf16.bf16.f32 "
                 "{%0,%1,%2,%3},{%4,%5,%6,%7},{%8,%9},{%0,%1,%2,%3};"
                 : "+f"(d[0]), "+f"(d[1]), "+f"(d[2]), "+f"(d[3])
                 : "r"(a[0]), "r"(a[1]), "r"(a[2]), "r"(a[3]),
                   "r"(b[0]), "r"(b[1]));
}
__device__ __forceinline__ void cpasync16(uint32_t dst, const void* src) {
    asm volatile("cp.async.cg.shared.global [%0], [%1], 16;"
                 :: "r"(dst), "l"(src) : "memory");
}
__device__ __forceinline__ void cpcommit() {
    asm volatile("cp.async.commit_group;" ::: "memory");
}
__device__ __forceinline__ void cpwait0() {
    asm volatile("cp.async.wait_group 0;" ::: "memory");
}

// ---- weight preprocessing: split bf16 hi/lo, kk-major, 144B row stride ------
__global__ __launch_bounds__(256) void prep_weights(WParams P)
{
    int ch = blockIdx.x;
    int s = 0;
    #pragma unroll
    for (int i = 1; i < 6; i++) if (ch >= d_wch0[i]) s = i;
    int cis = ch - d_wch0[s];
    int C = d_C[s];
    int K = C * 9;
    int k0 = cis * 64;
    int kk = k0 >> d_logC[s];
    int c0 = k0 & (C - 1);
    size_t base = (size_t)ch * WCHUNK;

    for (int e = threadIdx.x; e < 152 * 64; e += blockDim.x) {
        int row = e >> 6;
        int col = e & 63;
        float v = 0.f;
        if (row < 150) {
            int widx = (c0 + col) * 9 + kk;
            v = (row < 24) ? P.lw[s][(size_t)row * K + widx]
                           : P.cw[s][(size_t)(row - 24) * K + widx];
        }
        __nv_bfloat16 h = __float2bfloat16(v);
        __nv_bfloat16 l = __float2bfloat16(v - __bfloat162float(h));
        size_t off = base + (size_t)row * RS + col * 2;
        *(__nv_bfloat16*)(g_wbf + off) = h;
        *(__nv_bfloat16*)(g_wbf + off + WTILE) = l;
    }
}

// ---- main fused kernel --------------------------------------------------------
__global__ __launch_bounds__(NTH, 1) void ssd_hmma_kernel(
    CParams P, const float* __restrict__ priors, float* __restrict__ out)
{
    extern __shared__ __align__(16) unsigned char sm[];
    float* Dsm = (float*)sm;
    const uint32_t smb = smaddr(sm);

    const int tid = threadIdx.x;
    const int wid = tid >> 5;
    const int lane = tid & 31;
    const int mt8 = wid & 7;              // m-tile: 16 pixels per warp
    const int grp = wid >> 3;             // 0: n-tiles 0..9, 1: n-tiles 10..18

    // ---- block -> (stage, pixel tile) ----
    int bid = blockIdx.x;
    int oi = 0;
    #pragma unroll
    for (int i = 1; i < 6; i++) if (bid >= d_bstart[i]) oi = i;
    const int s = d_border[oi];
    const int pix0 = (bid - d_bstart[oi]) * 128;

    const int C = d_C[s], logC = d_logC[s], F = d_F[s], FF = d_FF[s], N = d_N[s];
    const int nch = d_nch[s], wch0 = d_wch0[s];
    const float* __restrict__ feat = P.feat[s];

    // ---- A gather geometry: 4 threads per pixel row, 16 k-values each ----
    const int arow = tid >> 2;              // 0..127
    const int aq   = (tid & 3) * 16;        // k offset within 64-chunk
    const int apix = pix0 + arow;
    const bool aok = (apix < N);
    int ab = 0, ay = 0, ax = 0;
    if (aok) {
        ab = apix / FF;
        int r = apix - ab * FF;
        ay = r / F;
        ax = r - ay * F;
    }
    const float* fb0 = feat + (size_t)ab * C * FF;

    // ---- ldmatrix lane address components ----
    const int a_mloc = (lane & 7) + ((lane >> 3) & 1) * 8;
    const int a_kg   = lane >> 4;
    const int b_nloc = (lane & 7) + (lane >> 4) * 8;
    const int b_kg   = (lane >> 3) & 1;
    const int b_nloc2 = lane & 7;

    float acc[10][4];
    #pragma unroll
    for (int nt = 0; nt < 10; nt++)
        #pragma unroll
        for (int q = 0; q < 4; q++) acc[nt][q] = 0.f;

    // ---------------- helpers ----------------
    auto copyB = [&](int ch, int buf) {
        const uint4* src = (const uint4*)(g_wbf + (size_t)(wch0 + ch) * WCHUNK);
        uint32_t dst = smb + buf * BUFSZ + B_HI;
        #pragma unroll 2
        for (int i = tid; i < WCHUNK / 16; i += NTH)
            cpasync16(dst + i * 16, src + i);
    };
    float xg[16];
    auto gatherA = [&](int ch) {
        int k0 = ch * 64;
        int kk = k0 >> logC;
        int c0 = k0 & (C - 1);
        int ky = kk / 3, kx = kk - ky * 3;
        int iy = ay + ky - 1, ix = ax + kx - 1;
        bool v = aok && ((unsigned)iy < (unsigned)F) && ((unsigned)ix < (unsigned)F);
        const float* bp = fb0 + (size_t)(c0 + aq) * FF + iy * F + ix;
        #pragma unroll
        for (int j = 0; j < 16; j++)
            xg[j] = v ? __ldg(bp + (size_t)j * FF) : 0.f;
    };
    auto storeA = [&](int buf) {
        unsigned char* b = sm + buf * BUFSZ;
        #pragma unroll
        for (int j = 0; j < 16; j += 2) {
            __nv_bfloat16 h0 = __float2bfloat16(xg[j]);
            __nv_bfloat16 h1 = __float2bfloat16(xg[j + 1]);
            __nv_bfloat16 l0 = __float2bfloat16(xg[j] - __bfloat162float(h0));
            __nv_bfloat16 l1 = __float2bfloat16(xg[j + 1] - __bfloat162float(h1));
            uint32_t off = arow * RS + (aq + j) * 2;
            *(uint32_t*)(b + A_HI + off) =
                (uint32_t)__bfloat16_as_ushort(h0) | ((uint32_t)__bfloat16_as_ushort(h1) << 16);
            *(uint32_t*)(b + A_LO + off) =
                (uint32_t)__bfloat16_as_ushort(l0) | ((uint32_t)__bfloat16_as_ushort(l1) << 16);
        }
    };
    auto compute = [&](int buf) {
        const uint32_t ba = smb + buf * BUFSZ;
        #pragma unroll
        for (int k16 = 0; k16 < 4; k16++) {
            const uint32_t kgran = (uint32_t)k16 * 32;
            uint32_t ah[4], al[4];
            uint32_t ra = (uint32_t)(mt8 * 16 + a_mloc) * RS + kgran + a_kg * 16;
            ldsm4(ah, ba + A_HI + ra);
            ldsm4(al, ba + A_LO + ra);
            if (grp == 0) {
                #pragma unroll
                for (int g = 0; g < 2; g++) {      // n-tiles 4g .. 4g+3
                    int j = g * 4;
                    uint32_t bh[8], bl[8];
                    uint32_t br0 = (uint32_t)(j * 8 + b_nloc) * RS + kgran + b_kg * 16;
                    uint32_t br1 = (uint32_t)((j + 2) * 8 + b_nloc) * RS + kgran + b_kg * 16;
                    ldsm4(bh,     ba + B_HI + br0);
                    ldsm4(bh + 4, ba + B_HI + br1);
                    ldsm4(bl,     ba + B_LO + br0);
                    ldsm4(bl + 4, ba + B_LO + br1);
                    mma16816(acc[j],     ah, bh);
                    mma16816(acc[j + 1], ah, bh + 2);
                    mma16816(acc[j + 2], ah, bh + 4);
                    mma16816(acc[j + 3], ah, bh + 6);
                    mma16816(acc[j],     ah, bl);
                    mma16816(acc[j + 1], ah, bl + 2);
                    mma16816(acc[j + 2], ah, bl + 4);
                    mma16816(acc[j + 3], ah, bl + 6);
                    mma16816(acc[j],     al, bh);
                    mma16816(acc[j + 1], al, bh + 2);
                    mma16816(acc[j + 2], al, bh + 4);
                    mma16816(acc[j + 3], al, bh + 6);
                }
                {   // n-tiles 8, 9
                    uint32_t bh[4], bl[4];
                    uint32_t br = (uint32_t)(64 + b_nloc) * RS + kgran + b_kg * 16;
                    ldsm4(bh, ba + B_HI + br);
                    ldsm4(bl, ba + B_LO + br);
                    mma16816(acc[8], ah, bh);
                    mma16816(acc[9], ah, bh + 2);
                    mma16816(acc[8], ah, bl);
                    mma16816(acc[9], ah, bl + 2);
                    mma16816(acc[8], al, bh);
                    mma16816(acc[9], al, bh + 2);
                }
            } else {
                #pragma unroll
                for (int g = 0; g < 2; g++) {      // global n-tiles 10+4g .. 13+4g
                    int j = g * 4;
                    uint32_t bh[8], bl[8];
                    uint32_t br0 = (uint32_t)(80 + j * 8 + b_nloc) * RS + kgran + b_kg * 16;
                    uint32_t br1 = (uint32_t)(80 + (j + 2) * 8 + b_nloc) * RS + kgran + b_kg * 16;
                    ldsm4(bh,     ba + B_HI + br0);
                    ldsm4(bh + 4, ba + B_HI + br1);
                    ldsm4(bl,     ba + B_LO + br0);
                    ldsm4(bl + 4, ba + B_LO + br1);
                    mma16816(acc[j],     ah, bh);
                    mma16816(acc[j + 1], ah, bh + 2);
                    mma16816(acc[j + 2], ah, bh + 4);
                    mma16816(acc[j + 3], ah, bh + 6);
                    mma16816(acc[j],     ah, bl);
                    mma16816(acc[j + 1], ah, bl + 2);
                    mma16816(acc[j + 2], ah, bl + 4);
                    mma16816(acc[j + 3], ah, bl + 6);
                    mma16816(acc[j],     al, bh);
                    mma16816(acc[j + 1], al, bh + 2);
                    mma16816(acc[j + 2], al, bh + 4);
                    mma16816(acc[j + 3], al, bh + 6);
                }
                {   // global n-tile 18 (local 8), x2
                    uint32_t bh[2], bl[2];
                    uint32_t br = (uint32_t)(144 + b_nloc2) * RS + kgran + b_kg * 16;
                    ldsm2(bh, ba + B_HI + br);
                    ldsm2(bl, ba + B_LO + br);
                    mma16816(acc[8], ah, bh);
                    mma16816(acc[8], ah, bl);
                    mma16816(acc[8], al, bh);
                }
            }
        }
    };

    // ---------------- pipeline ----------------
    copyB(0, 0);
    cpcommit();
    gatherA(0);
    storeA(0);
    cpwait0();
    __syncthreads();

    for (int ch = 0; ch < nch; ch++) {
        int cur = ch & 1;
        bool pf = (ch + 1 < nch);
        if (pf) {
            copyB(ch + 1, cur ^ 1);
            cpcommit();
            gatherA(ch + 1);        // LDGs in flight during MMAs
        }
        compute(cur);
        if (pf) storeA(cur ^ 1);    // convert + STS after MMAs
        cpwait0();
        __syncthreads();
    }

    // ---- write accumulators to smem D[128][153] ----
    {
        const int ntl = grp ? 9 : 10;
        const int colb = grp ? 80 : 0;
        #pragma unroll
        for (int nt = 0; nt < 10; nt++) {
            if (nt >= ntl) break;
            int r = mt8 * 16 + (lane >> 2);
            int c = colb + nt * 8 + (lane & 3) * 2;
            Dsm[r * 153 + c]           = acc[nt][0];
            Dsm[r * 153 + c + 1]       = acc[nt][1];
            Dsm[(r + 8) * 153 + c]     = acc[nt][2];
            Dsm[(r + 8) * 153 + c + 1] = acc[nt][3];
        }
    }
    __syncthreads();

    // ---- per-pixel bias + decode + softmax ----
    if (tid < 128) {
        int n = pix0 + tid;
        if (n < N) {
            const float* drow = Dsm + tid * 153;
            int b = n / FF;
            int r = n - b * FF;
            int pbase = d_poff[s] + r * 6;
            float* ob = out + ((size_t)b * NUM_PRIORS + pbase) * 25;
            const float* lb = P.lb[s];
            const float* cb = P.cb[s];
            #pragma unroll
            for (int pic = 0; pic < 6; pic++) {
                const float* pr = priors + (size_t)(pbase + pic) * 4;
                float prx = __ldg(pr + 0), pry = __ldg(pr + 1);
                float prz = __ldg(pr + 2), prw = __ldg(pr + 3);
                float lx = drow[pic * 4 + 0] + __ldg(lb + pic * 4 + 0);
                float ly = drow[pic * 4 + 1] + __ldg(lb + pic * 4 + 1);
                float lw_ = drow[pic * 4 + 2] + __ldg(lb + pic * 4 + 2);
                float lh_ = drow[pic * 4 + 3] + __ldg(lb + pic * 4 + 3);
                float cx = prx + lx * 0.1f * prz;
                float cy = pry + ly * 0.1f * prw;
                float w = prz * expf(lw_ * 0.2f);
                float h = prw * expf(lh_ * 0.2f);
                float mnx = cx - 0.5f * w;
                float mny = cy - 0.5f * h;
                float* o = ob + pic * 25;
                o[0] = mnx; o[1] = mny; o[2] = mnx + w; o[3] = mny + h;

                float vv[21];
                float mx = -1e30f;
                #pragma unroll
                for (int c2 = 0; c2 < 21; c2++) {
                    vv[c2] = drow[24 + pic * 21 + c2] + __ldg(cb + pic * 21 + c2);
                    mx = fmaxf(mx, vv[c2]);
                }
                float ssum = 0.f;
                #pragma unroll
                for (int c2 = 0; c2 < 21; c2++) { vv[c2] = expf(vv[c2] - mx); ssum += vv[c2]; }
                float inv = 1.f / ssum;
                #pragma unroll
                for (int c2 = 0; c2 < 21; c2++) o[4 + c2] = vv[c2] * inv;
            }
        }
    }
}

// ---------------------------------------------------------------------------
extern "C" void kernel_launch(void* const* d_in, const int* in_sizes, int n_in,
                              void* d_out, int out_size)
{
    CParams cp;
    WParams wp;
    const float* priors;

    bool interleaved = (n_in == 31) && (in_sizes[2] == 24);
    if (interleaved) {
        for (int s = 0; s < 6; s++) {
            cp.feat[s] = (const float*)d_in[s * 5 + 0];
            wp.lw[s]   = (const float*)d_in[s * 5 + 1];
            cp.lb[s]   = (const float*)d_in[s * 5 + 2];
            wp.cw[s]   = (const float*)d_in[s * 5 + 3];
            cp.cb[s]   = (const float*)d_in[s * 5 + 4];
        }
        priors = (const float*)d_in[30];
    } else {
        for (int s = 0; s < 6; s++) {
            cp.feat[s] = (const float*)d_in[s];
            wp.lw[s]   = (const float*)d_in[6 + s];
            cp.lb[s]   = (const float*)d_in[12 + s];
            wp.cw[s]   = (const float*)d_in[18 + s];
            cp.cb[s]   = (const float*)d_in[24 + s];
        }
        priors = (const float*)d_in[30];
    }

    cudaFuncSetAttribute(ssd_hmma_kernel,
                         cudaFuncAttributeMaxDynamicSharedMemorySize, SMEM_BYTES);

    prep_weights<<<TOTAL_WCHUNKS, 256>>>(wp);
    ssd_hmma_kernel<<<TOTAL_BLOCKS, NTH, SMEM_BYTES>>>(cp, priors, (float*)d_out);
}

// round 9
// speedup vs baseline: 7.6754x; 1.1168x over previous
#include <cuda_runtime.h>
#include <cuda_bf16.h>
#include <stdint.h>

// ---------------------------------------------------------------------------
// SSD head via warp-level mma.sync m16n8k8 TF32 (single pass, RNA-rounded),
// round 9. The mma.sync issue rate (~16 cyc/instr/SMSP) is the binder, so we
// cut instruction count 3->2 per k16 by replacing the 3-term bf16 split with
// single-pass tf32 (error ~3e-4 < 1e-3 budget). 512 thr / 16 warps per CTA,
// warp (wid&7) -> m-tile, (wid>>3) -> n-group. Double-buffered smem
// (cp.async B copy + pipelined A gather). Epilogue: bias+decode+softmax.
// ---------------------------------------------------------------------------

#define NUM_PRIORS 11640
#define NTH 512
#define RS 272                          // smem row stride bytes (68 words; 68%32=4 -> LDSM conflict-free)
#define ATILE (128 * RS)                // 34816
#define BTILE (152 * RS)                // 41344
#define TOTAL_WCHUNKS 396
#define TOTAL_BLOCKS 488
#define A_OFF 0
#define B_OFF ATILE
#define BUFSZ (ATILE + BTILE)           // 76160
#define SMEM_BYTES (2 * BUFSZ)          // 152320

__device__ __constant__ int d_C[6]    = {512,1024,512,256,256,256};
__device__ __constant__ int d_logC[6] = {9,10,9,8,8,8};
__device__ __constant__ int d_F[6]    = {38,19,10,5,3,1};
__device__ __constant__ int d_FF[6]   = {1444,361,100,25,9,1};
__device__ __constant__ int d_N[6]    = {46208,11552,3200,800,288,32};
__device__ __constant__ int d_nch[6]  = {72,144,72,36,36,36};
__device__ __constant__ int d_wch0[6] = {0,72,216,288,324,360};
__device__ __constant__ int d_poff[6] = {0,8664,10830,11430,11580,11634};
__device__ __constant__ int d_bstart[7] = {0,91,452,477,484,487,488};
__device__ __constant__ int d_border[6] = {1,0,2,3,4,5};

__device__ unsigned char g_wbf[(size_t)TOTAL_WCHUNKS * BTILE];

struct WParams { const float* lw[6]; const float* cw[6]; };
struct CParams { const float* feat[6]; const float* lb[6]; const float* cb[6]; };

// ---- PTX helpers ------------------------------------------------------------
__device__ __forceinline__ uint32_t smaddr(const void* p) {
    return (uint32_t)__cvta_generic_to_shared(p);
}
__device__ __forceinline__ uint32_t to_tf32(float x) {
    uint32_t u;
    asm("cvt.rna.tf32.f32 %0, %1;" : "=r"(u) : "f"(x));
    return u;
}
__device__ __forceinline__ void ldsm4(uint32_t* r, uint32_t a) {
    asm volatile("ldmatrix.sync.aligned.m8n8.x4.shared.b16 {%0,%1,%2,%3}, [%4];"
                 : "=r"(r[0]), "=r"(r[1]), "=r"(r[2]), "=r"(r[3]) : "r"(a));
}
__device__ __forceinline__ void ldsm2(uint32_t* r, uint32_t a) {
    asm volatile("ldmatrix.sync.aligned.m8n8.x2.shared.b16 {%0,%1}, [%2];"
                 : "=r"(r[0]), "=r"(r[1]) : "r"(a));
}
__device__ __forceinline__ void mma_tf32(float* d, const uint32_t* a, const uint32_t* b) {
    asm volatile("mma.sync.aligned.m16n8k8.row.col.f32.tf32.tf32.f32 "
                 "{%0,%1,%2,%3},{%4,%5,%6,%7},{%8,%9},{%0,%1,%2,%3};"
                 : "+f"(d[0]), "+f"(d[1]), "+f"(d[2]), "+f"(d[3])
                 : "r"(a[0]), "r"(a[1]), "r"(a[2]), "r"(a[3]),
                   "r"(b[0]), "r"(b[1]));
}
__device__ __forceinline__ void cpasync16(uint32_t dst, const void* src) {
    asm volatile("cp.async.cg.shared.global [%0], [%1], 16;"
                 :: "r"(dst), "l"(src) : "memory");
}
__device__ __forceinline__ void cpcommit() {
    asm volatile("cp.async.commit_group;" ::: "memory");
}
__device__ __forceinline__ void cpwait0() {
    asm volatile("cp.async.wait_group 0;" ::: "memory");
}

// ---- weight preprocessing: RNA-rounded tf32 image, kk-major, RS-stride ------
__global__ __launch_bounds__(256) void prep_weights(WParams P)
{
    int ch = blockIdx.x;
    int s = 0;
    #pragma unroll
    for (int i = 1; i < 6; i++) if (ch >= d_wch0[i]) s = i;
    int cis = ch - d_wch0[s];
    int C = d_C[s];
    int K = C * 9;
    int k0 = cis * 64;
    int kk = k0 >> d_logC[s];
    int c0 = k0 & (C - 1);
    size_t base = (size_t)ch * BTILE;

    for (int e = threadIdx.x; e < 152 * 64; e += blockDim.x) {
        int row = e >> 6;
        int col = e & 63;
        float v = 0.f;
        if (row < 150) {
            int widx = (c0 + col) * 9 + kk;
            v = (row < 24) ? P.lw[s][(size_t)row * K + widx]
                           : P.cw[s][(size_t)(row - 24) * K + widx];
        }
        *(uint32_t*)(g_wbf + base + (size_t)row * RS + col * 4) = to_tf32(v);
    }
}

// ---- main fused kernel --------------------------------------------------------
__global__ __launch_bounds__(NTH, 1) void ssd_tf32_kernel(
    CParams P, const float* __restrict__ priors, float* __restrict__ out)
{
    extern __shared__ __align__(16) unsigned char sm[];
    float* Dsm = (float*)sm;
    const uint32_t smb = smaddr(sm);

    const int tid = threadIdx.x;
    const int wid = tid >> 5;
    const int lane = tid & 31;
    const int mt8 = wid & 7;              // m-tile: 16 pixels per warp
    const int grp = wid >> 3;             // 0: n-tiles 0..9, 1: n-tiles 10..18

    // ---- block -> (stage, pixel tile) ----
    int bid = blockIdx.x;
    int oi = 0;
    #pragma unroll
    for (int i = 1; i < 6; i++) if (bid >= d_bstart[i]) oi = i;
    const int s = d_border[oi];
    const int pix0 = (bid - d_bstart[oi]) * 128;

    const int C = d_C[s], logC = d_logC[s], F = d_F[s], FF = d_FF[s], N = d_N[s];
    const int nch = d_nch[s], wch0 = d_wch0[s];
    const float* __restrict__ feat = P.feat[s];

    // ---- A gather geometry: 4 threads per pixel row, 16 k-values each ----
    const int arow = tid >> 2;              // 0..127
    const int aq   = (tid & 3) * 16;        // k offset within 64-chunk
    const int apix = pix0 + arow;
    const bool aok = (apix < N);
    int ab = 0, ay = 0, ax = 0;
    if (aok) {
        ab = apix / FF;
        int r = apix - ab * FF;
        ay = r / F;
        ax = r - ay * F;
    }
    const float* fb0 = feat + (size_t)ab * C * FF;

    // ---- ldmatrix lane address components ----
    const int a_mloc = (lane & 7) + ((lane >> 3) & 1) * 8;   // m-row 0..15
    const int a_kg   = lane >> 4;                             // +16B (tf32 cols 4-7)
    const int b_r    = lane & 7;
    const int b_half = (lane >> 3) & 1;                       // +16B
    const int b_tl   = (lane >> 4) & 1;                       // n-tile pair member

    float acc[10][4];
    #pragma unroll
    for (int nt = 0; nt < 10; nt++)
        #pragma unroll
        for (int q = 0; q < 4; q++) acc[nt][q] = 0.f;

    // ---------------- helpers ----------------
    auto copyB = [&](int ch, int buf) {
        const uint4* src = (const uint4*)(g_wbf + (size_t)(wch0 + ch) * BTILE);
        uint32_t dst = smb + buf * BUFSZ + B_OFF;
        #pragma unroll 3
        for (int i = tid; i < BTILE / 16; i += NTH)
            cpasync16(dst + i * 16, src + i);
    };
    float xg[16];
    auto gatherA = [&](int ch) {
        int k0 = ch * 64;
        int kk = k0 >> logC;
        int c0 = k0 & (C - 1);
        int ky = kk / 3, kx = kk - ky * 3;
        int iy = ay + ky - 1, ix = ax + kx - 1;
        bool v = aok && ((unsigned)iy < (unsigned)F) && ((unsigned)ix < (unsigned)F);
        const float* bp = fb0 + (size_t)(c0 + aq) * FF + iy * F + ix;
        #pragma unroll
        for (int j = 0; j < 16; j++)
            xg[j] = v ? __ldg(bp + (size_t)j * FF) : 0.f;
    };
    auto storeA = [&](int buf) {
        uint32_t t[16];
        #pragma unroll
        for (int j = 0; j < 16; j++) t[j] = to_tf32(xg[j]);
        uint32_t base = smb + buf * BUFSZ + A_OFF + arow * RS + aq * 4;
        #pragma unroll
        for (int j = 0; j < 16; j += 4) {
            asm volatile("st.shared.v4.b32 [%0], {%1,%2,%3,%4};"
                         :: "r"(base + j * 4),
                            "r"(t[j]), "r"(t[j + 1]), "r"(t[j + 2]), "r"(t[j + 3])
                         : "memory");
        }
    };
    auto compute = [&](int buf) {
        const uint32_t aB = smb + buf * BUFSZ + A_OFF;
        const uint32_t bB = smb + buf * BUFSZ + B_OFF;
        #pragma unroll
        for (int k8 = 0; k8 < 8; k8++) {
            const uint32_t kb = (uint32_t)k8 * 32;
            uint32_t a[4];
            ldsm4(a, aB + (uint32_t)(mt8 * 16 + a_mloc) * RS + kb + a_kg * 16);
            if (grp == 0) {
                #pragma unroll
                for (int g = 0; g < 5; g++) {      // n-tile pair (2g, 2g+1)
                    int j = g * 2;
                    uint32_t bb[4];
                    uint32_t br = (uint32_t)((j + b_tl) * 8 + b_r) * RS + kb + b_half * 16;
                    ldsm4(bb, bB + br);
                    mma_tf32(acc[j],     a, bb);
                    mma_tf32(acc[j + 1], a, bb + 2);
                }
            } else {
                #pragma unroll
                for (int g = 0; g < 4; g++) {      // global n-tile pair (10+2g, 11+2g)
                    int j = g * 2;
                    uint32_t bb[4];
                    uint32_t br = (uint32_t)(80 + (j + b_tl) * 8 + b_r) * RS + kb + b_half * 16;
                    ldsm4(bb, bB + br);
                    mma_tf32(acc[j],     a, bb);
                    mma_tf32(acc[j + 1], a, bb + 2);
                }
                {   // global n-tile 18 (local 8)
                    uint32_t bb[2];
                    uint32_t br = (uint32_t)(144 + b_r) * RS + kb + b_half * 16;
                    ldsm2(bb, bB + br);
                    mma_tf32(acc[8], a, bb);
                }
            }
        }
    };

    // ---------------- pipeline ----------------
    copyB(0, 0);
    cpcommit();
    gatherA(0);
    storeA(0);
    cpwait0();
    __syncthreads();

    for (int ch = 0; ch < nch; ch++) {
        int cur = ch & 1;
        bool pf = (ch + 1 < nch);
        if (pf) {
            copyB(ch + 1, cur ^ 1);
            cpcommit();
            gatherA(ch + 1);        // LDGs in flight during MMAs
        }
        compute(cur);
        if (pf) storeA(cur ^ 1);    // round + STS after MMAs
        cpwait0();
        __syncthreads();
    }

    // ---- write accumulators to smem D[128][153] ----
    {
        const int ntl = grp ? 9 : 10;
        const int colb = grp ? 80 : 0;
        #pragma unroll
        for (int nt = 0; nt < 10; nt++) {
            if (nt >= ntl) break;
            int r = mt8 * 16 + (lane >> 2);
            int c = colb + nt * 8 + (lane & 3) * 2;
            Dsm[r * 153 + c]           = acc[nt][0];
            Dsm[r * 153 + c + 1]       = acc[nt][1];
            Dsm[(r + 8) * 153 + c]     = acc[nt][2];
            Dsm[(r + 8) * 153 + c + 1] = acc[nt][3];
        }
    }
    __syncthreads();

    // ---- per-pixel bias + decode + softmax ----
    if (tid < 128) {
        int n = pix0 + tid;
        if (n < N) {
            const float* drow = Dsm + tid * 153;
            int b = n / FF;
            int r = n - b * FF;
            int pbase = d_poff[s] + r * 6;
            float* ob = out + ((size_t)b * NUM_PRIORS + pbase) * 25;
            const float* lb = P.lb[s];
            const float* cb = P.cb[s];
            #pragma unroll
            for (int pic = 0; pic < 6; pic++) {
                const float* pr = priors + (size_t)(pbase + pic) * 4;
                float prx = __ldg(pr + 0), pry = __ldg(pr + 1);
                float prz = __ldg(pr + 2), prw = __ldg(pr + 3);
                float lx = drow[pic * 4 + 0] + __ldg(lb + pic * 4 + 0);
                float ly = drow[pic * 4 + 1] + __ldg(lb + pic * 4 + 1);
                float lw_ = drow[pic * 4 + 2] + __ldg(lb + pic * 4 + 2);
                float lh_ = drow[pic * 4 + 3] + __ldg(lb + pic * 4 + 3);
                float cx = prx + lx * 0.1f * prz;
                float cy = pry + ly * 0.1f * prw;
                float w = prz * expf(lw_ * 0.2f);
                float h = prw * expf(lh_ * 0.2f);
                float mnx = cx - 0.5f * w;
                float mny = cy - 0.5f * h;
                float* o = ob + pic * 25;
                o[0] = mnx; o[1] = mny; o[2] = mnx + w; o[3] = mny + h;

                float vv[21];
                float mx = -1e30f;
                #pragma unroll
                for (int c2 = 0; c2 < 21; c2++) {
                    vv[c2] = drow[24 + pic * 21 + c2] + __ldg(cb + pic * 21 + c2);
                    mx = fmaxf(mx, vv[c2]);
                }
                float ssum = 0.f;
                #pragma unroll
                for (int c2 = 0; c2 < 21; c2++) { vv[c2] = expf(vv[c2] - mx); ssum += vv[c2]; }
                float inv = 1.f / ssum;
                #pragma unroll
                for (int c2 = 0; c2 < 21; c2++) o[4 + c2] = vv[c2] * inv;
            }
        }
    }
}

// ---------------------------------------------------------------------------
extern "C" void kernel_launch(void* const* d_in, const int* in_sizes, int n_in,
                              void* d_out, int out_size)
{
    CParams cp;
    WParams wp;
    const float* priors;

    bool interleaved = (n_in == 31) && (in_sizes[2] == 24);
    if (interleaved) {
        for (int s = 0; s < 6; s++) {
            cp.feat[s] = (const float*)d_in[s * 5 + 0];
            wp.lw[s]   = (const float*)d_in[s * 5 + 1];
            cp.lb[s]   = (const float*)d_in[s * 5 + 2];
            wp.cw[s]   = (const float*)d_in[s * 5 + 3];
            cp.cb[s]   = (const float*)d_in[s * 5 + 4];
        }
        priors = (const float*)d_in[30];
    } else {
        for (int s = 0; s < 6; s++) {
            cp.feat[s] = (const float*)d_in[s];
            wp.lw[s]   = (const float*)d_in[6 + s];
            cp.lb[s]   = (const float*)d_in[12 + s];
            wp.cw[s]   = (const float*)d_in[18 + s];
            cp.cb[s]   = (const float*)d_in[24 + s];
        }
        priors = (const float*)d_in[30];
    }

    cudaFuncSetAttribute(ssd_tf32_kernel,
                         cudaFuncAttributeMaxDynamicSharedMemorySize, SMEM_BYTES);

    prep_weights<<<TOTAL_WCHUNKS, 256>>>(wp);
    ssd_tf32_kernel<<<TOTAL_BLOCKS, NTH, SMEM_BYTES>>>(cp, priors, (float*)d_out);
}

// round 10
// speedup vs baseline: 8.2873x; 1.0797x over previous
#include <cuda_runtime.h>
#include <cuda_bf16.h>
#include <stdint.h>

// ---------------------------------------------------------------------------
// SSD head via mma.sync m16n8k8 TF32, round 10: warp grid re-tiled to
// 4 m-groups x 4 n-groups (each warp: 2 m-tiles x 5 n-tiles) so each B
// fragment feeds 2 m-tiles -> LDSM bytes/MMA drop ~26%, moving the binder
// from L1/LSU back to the tensor pipe. LDSM base addresses hoisted out of
// the k8 loop. Double-buffered smem (cp.async B + pipelined A gather).
// Epilogue: acc -> smem -> bias + box decode + softmax inline.
// ---------------------------------------------------------------------------

#define NUM_PRIORS 11640
#define NTH 512
#define RS 272                          // smem row stride bytes (68 words; %32=4 -> conflict-free LDSM)
#define ATILE (128 * RS)                // 34816
#define BTILE (152 * RS)                // 41344
#define TOTAL_WCHUNKS 396
#define TOTAL_BLOCKS 488
#define A_OFF 0
#define B_OFF ATILE
#define BUFSZ (ATILE + BTILE)           // 76160
#define SMEM_BYTES (2 * BUFSZ)          // 152320

__device__ __constant__ int d_C[6]    = {512,1024,512,256,256,256};
__device__ __constant__ int d_logC[6] = {9,10,9,8,8,8};
__device__ __constant__ int d_F[6]    = {38,19,10,5,3,1};
__device__ __constant__ int d_FF[6]   = {1444,361,100,25,9,1};
__device__ __constant__ int d_N[6]    = {46208,11552,3200,800,288,32};
__device__ __constant__ int d_nch[6]  = {72,144,72,36,36,36};
__device__ __constant__ int d_wch0[6] = {0,72,216,288,324,360};
__device__ __constant__ int d_poff[6] = {0,8664,10830,11430,11580,11634};
__device__ __constant__ int d_bstart[7] = {0,91,452,477,484,487,488};
__device__ __constant__ int d_border[6] = {1,0,2,3,4,5};

__device__ unsigned char g_wbf[(size_t)TOTAL_WCHUNKS * BTILE];

struct WParams { const float* lw[6]; const float* cw[6]; };
struct CParams { const float* feat[6]; const float* lb[6]; const float* cb[6]; };

// ---- PTX helpers ------------------------------------------------------------
__device__ __forceinline__ uint32_t smaddr(const void* p) {
    return (uint32_t)__cvta_generic_to_shared(p);
}
__device__ __forceinline__ uint32_t to_tf32(float x) {
    uint32_t u;
    asm("cvt.rna.tf32.f32 %0, %1;" : "=r"(u) : "f"(x));
    return u;
}
__device__ __forceinline__ void ldsm4(uint32_t* r, uint32_t a) {
    asm volatile("ldmatrix.sync.aligned.m8n8.x4.shared.b16 {%0,%1,%2,%3}, [%4];"
                 : "=r"(r[0]), "=r"(r[1]), "=r"(r[2]), "=r"(r[3]) : "r"(a));
}
__device__ __forceinline__ void ldsm2(uint32_t* r, uint32_t a) {
    asm volatile("ldmatrix.sync.aligned.m8n8.x2.shared.b16 {%0,%1}, [%2];"
                 : "=r"(r[0]), "=r"(r[1]) : "r"(a));
}
__device__ __forceinline__ void mma_tf32(float* d, const uint32_t* a, const uint32_t* b) {
    asm volatile("mma.sync.aligned.m16n8k8.row.col.f32.tf32.tf32.f32 "
                 "{%0,%1,%2,%3},{%4,%5,%6,%7},{%8,%9},{%0,%1,%2,%3};"
                 : "+f"(d[0]), "+f"(d[1]), "+f"(d[2]), "+f"(d[3])
                 : "r"(a[0]), "r"(a[1]), "r"(a[2]), "r"(a[3]),
                   "r"(b[0]), "r"(b[1]));
}
__device__ __forceinline__ void cpasync16(uint32_t dst, const void* src) {
    asm volatile("cp.async.cg.shared.global [%0], [%1], 16;"
                 :: "r"(dst), "l"(src) : "memory");
}
__device__ __forceinline__ void cpcommit() {
    asm volatile("cp.async.commit_group;" ::: "memory");
}
__device__ __forceinline__ void cpwait0() {
    asm volatile("cp.async.wait_group 0;" ::: "memory");
}

// ---- weight preprocessing: RNA-rounded tf32 image, kk-major, RS-stride ------
__global__ __launch_bounds__(256) void prep_weights(WParams P)
{
    int ch = blockIdx.x;
    int s = 0;
    #pragma unroll
    for (int i = 1; i < 6; i++) if (ch >= d_wch0[i]) s = i;
    int cis = ch - d_wch0[s];
    int C = d_C[s];
    int K = C * 9;
    int k0 = cis * 64;
    int kk = k0 >> d_logC[s];
    int c0 = k0 & (C - 1);
    size_t base = (size_t)ch * BTILE;

    for (int e = threadIdx.x; e < 152 * 64; e += blockDim.x) {
        int row = e >> 6;
        int col = e & 63;
        float v = 0.f;
        if (row < 150) {
            int widx = (c0 + col) * 9 + kk;
            v = (row < 24) ? P.lw[s][(size_t)row * K + widx]
                           : P.cw[s][(size_t)(row - 24) * K + widx];
        }
        *(uint32_t*)(g_wbf + base + (size_t)row * RS + col * 4) = to_tf32(v);
    }
}

// ---- main fused kernel --------------------------------------------------------
__global__ __launch_bounds__(NTH, 1) void ssd_tf32_kernel(
    CParams P, const float* __restrict__ priors, float* __restrict__ out)
{
    extern __shared__ __align__(16) unsigned char sm[];
    float* Dsm = (float*)sm;
    const uint32_t smb = smaddr(sm);

    const int tid = threadIdx.x;
    const int wid = tid >> 5;
    const int lane = tid & 31;
    const int mg = wid & 3;               // m-group: 32 pixels (2 m-tiles)
    const int ng = wid >> 2;              // n-group: 5 tiles (ng3: 4 tiles)
    const int gbase = ng * 5;             // first global n-tile of group
    const int ntl = (ng == 3) ? 4 : 5;    // tiles in this group

    // ---- block -> (stage, pixel tile) ----
    int bid = blockIdx.x;
    int oi = 0;
    #pragma unroll
    for (int i = 1; i < 6; i++) if (bid >= d_bstart[i]) oi = i;
    const int s = d_border[oi];
    const int pix0 = (bid - d_bstart[oi]) * 128;

    const int C = d_C[s], logC = d_logC[s], F = d_F[s], FF = d_FF[s], N = d_N[s];
    const int nch = d_nch[s], wch0 = d_wch0[s];
    const float* __restrict__ feat = P.feat[s];

    // ---- A gather geometry: 4 threads per pixel row, 16 k-values each ----
    const int arow = tid >> 2;              // 0..127
    const int aq   = (tid & 3) * 16;        // k offset within 64-chunk
    const int apix = pix0 + arow;
    const bool aok = (apix < N);
    int ab = 0, ay = 0, ax = 0;
    if (aok) {
        ab = apix / FF;
        int r = apix - ab * FF;
        ay = r / F;
        ax = r - ay * F;
    }
    const float* fb0 = feat + (size_t)ab * C * FF;

    // ---- ldmatrix lane address components ----
    const int a_mloc = (lane & 7) + ((lane >> 3) & 1) * 8;   // m-row 0..15
    const int a_kg   = lane >> 4;                             // +16B (k cols 4..7)
    const int b_r    = lane & 7;
    const int b_half = (lane >> 3) & 1;                       // +16B
    const int b_tl   = (lane >> 4) & 1;                       // tile-pair member

    float acc[2][5][4];
    #pragma unroll
    for (int mt = 0; mt < 2; mt++)
        #pragma unroll
        for (int nt = 0; nt < 5; nt++)
            #pragma unroll
            for (int q = 0; q < 4; q++) acc[mt][nt][q] = 0.f;

    // ---------------- helpers ----------------
    auto copyB = [&](int ch, int buf) {
        const uint4* src = (const uint4*)(g_wbf + (size_t)(wch0 + ch) * BTILE);
        uint32_t dst = smb + buf * BUFSZ + B_OFF;
        #pragma unroll 3
        for (int i = tid; i < BTILE / 16; i += NTH)
            cpasync16(dst + i * 16, src + i);
    };
    float xg[16];
    auto gatherA = [&](int ch) {
        int k0 = ch * 64;
        int kk = k0 >> logC;
        int c0 = k0 & (C - 1);
        int ky = kk / 3, kx = kk - ky * 3;
        int iy = ay + ky - 1, ix = ax + kx - 1;
        bool v = aok && ((unsigned)iy < (unsigned)F) && ((unsigned)ix < (unsigned)F);
        const float* bp = fb0 + (size_t)(c0 + aq) * FF + iy * F + ix;
        #pragma unroll
        for (int j = 0; j < 16; j++)
            xg[j] = v ? __ldg(bp + (size_t)j * FF) : 0.f;
    };
    auto storeA = [&](int buf) {
        uint32_t t[16];
        #pragma unroll
        for (int j = 0; j < 16; j++) t[j] = to_tf32(xg[j]);
        uint32_t base = smb + buf * BUFSZ + A_OFF + arow * RS + aq * 4;
        #pragma unroll
        for (int j = 0; j < 16; j += 4) {
            asm volatile("st.shared.v4.b32 [%0], {%1,%2,%3,%4};"
                         :: "r"(base + j * 4),
                            "r"(t[j]), "r"(t[j + 1]), "r"(t[j + 2]), "r"(t[j + 3])
                         : "memory");
        }
    };
    auto compute = [&](int buf) {
        // hoisted base addresses (k8=0); advance by 32B per k8
        uint32_t aAd0 = smb + buf * BUFSZ + A_OFF
                      + (uint32_t)(mg * 32 + a_mloc) * RS + a_kg * 16;
        uint32_t aAd1 = aAd0 + 16 * RS;
        const uint32_t bB = smb + buf * BUFSZ + B_OFF;
        uint32_t bAd0 = bB + (uint32_t)((gbase + 0 + b_tl) * 8 + b_r) * RS + b_half * 16;
        uint32_t bAd1 = bB + (uint32_t)((gbase + 2 + b_tl) * 8 + b_r) * RS + b_half * 16;
        uint32_t bAd2 = bB + (uint32_t)((gbase + 4) * 8 + b_r) * RS + b_half * 16;
        #pragma unroll
        for (int k8 = 0; k8 < 8; k8++) {
            const uint32_t kb = (uint32_t)k8 * 32;
            uint32_t a0[4], a1[4];
            ldsm4(a0, aAd0 + kb);
            ldsm4(a1, aAd1 + kb);
            uint32_t b0[4], b1[4];
            ldsm4(b0, bAd0 + kb);
            ldsm4(b1, bAd1 + kb);
            // pair 0: tiles gbase, gbase+1
            mma_tf32(acc[0][0], a0, b0);
            mma_tf32(acc[1][0], a1, b0);
            mma_tf32(acc[0][1], a0, b0 + 2);
            mma_tf32(acc[1][1], a1, b0 + 2);
            // pair 1: tiles gbase+2, gbase+3
            mma_tf32(acc[0][2], a0, b1);
            mma_tf32(acc[1][2], a1, b1);
            mma_tf32(acc[0][3], a0, b1 + 2);
            mma_tf32(acc[1][3], a1, b1 + 2);
            if (ng != 3) {                    // single tile gbase+4
                uint32_t b2[2];
                ldsm2(b2, bAd2 + kb);
                mma_tf32(acc[0][4], a0, b2);
                mma_tf32(acc[1][4], a1, b2);
            }
        }
    };

    // ---------------- pipeline ----------------
    copyB(0, 0);
    cpcommit();
    gatherA(0);
    storeA(0);
    cpwait0();
    __syncthreads();

    for (int ch = 0; ch < nch; ch++) {
        int cur = ch & 1;
        bool pf = (ch + 1 < nch);
        if (pf) {
            copyB(ch + 1, cur ^ 1);
            cpcommit();
            gatherA(ch + 1);        // LDGs in flight during MMAs
        }
        compute(cur);
        if (pf) storeA(cur ^ 1);    // round + STS after MMAs
        cpwait0();
        __syncthreads();
    }

    // ---- write accumulators to smem D[128][153] ----
    #pragma unroll
    for (int mt = 0; mt < 2; mt++)
        #pragma unroll
        for (int nt = 0; nt < 5; nt++) {
            if (nt >= ntl) break;
            int r = mg * 32 + mt * 16 + (lane >> 2);
            int c = (gbase + nt) * 8 + (lane & 3) * 2;
            Dsm[r * 153 + c]           = acc[mt][nt][0];
            Dsm[r * 153 + c + 1]       = acc[mt][nt][1];
            Dsm[(r + 8) * 153 + c]     = acc[mt][nt][2];
            Dsm[(r + 8) * 153 + c + 1] = acc[mt][nt][3];
        }
    __syncthreads();

    // ---- per-pixel bias + decode + softmax ----
    if (tid < 128) {
        int n = pix0 + tid;
        if (n < N) {
            const float* drow = Dsm + tid * 153;
            int b = n / FF;
            int r = n - b * FF;
            int pbase = d_poff[s] + r * 6;
            float* ob = out + ((size_t)b * NUM_PRIORS + pbase) * 25;
            const float* lb = P.lb[s];
            const float* cb = P.cb[s];
            #pragma unroll
            for (int pic = 0; pic < 6; pic++) {
                const float* pr = priors + (size_t)(pbase + pic) * 4;
                float prx = __ldg(pr + 0), pry = __ldg(pr + 1);
                float prz = __ldg(pr + 2), prw = __ldg(pr + 3);
                float lx = drow[pic * 4 + 0] + __ldg(lb + pic * 4 + 0);
                float ly = drow[pic * 4 + 1] + __ldg(lb + pic * 4 + 1);
                float lw_ = drow[pic * 4 + 2] + __ldg(lb + pic * 4 + 2);
                float lh_ = drow[pic * 4 + 3] + __ldg(lb + pic * 4 + 3);
                float cx = prx + lx * 0.1f * prz;
                float cy = pry + ly * 0.1f * prw;
                float w = prz * expf(lw_ * 0.2f);
                float h = prw * expf(lh_ * 0.2f);
                float mnx = cx - 0.5f * w;
                float mny = cy - 0.5f * h;
                float* o = ob + pic * 25;
                o[0] = mnx; o[1] = mny; o[2] = mnx + w; o[3] = mny + h;

                float vv[21];
                float mx = -1e30f;
                #pragma unroll
                for (int c2 = 0; c2 < 21; c2++) {
                    vv[c2] = drow[24 + pic * 21 + c2] + __ldg(cb + pic * 21 + c2);
                    mx = fmaxf(mx, vv[c2]);
                }
                float ssum = 0.f;
                #pragma unroll
                for (int c2 = 0; c2 < 21; c2++) { vv[c2] = expf(vv[c2] - mx); ssum += vv[c2]; }
                float inv = 1.f / ssum;
                #pragma unroll
                for (int c2 = 0; c2 < 21; c2++) o[4 + c2] = vv[c2] * inv;
            }
        }
    }
}

// ---------------------------------------------------------------------------
extern "C" void kernel_launch(void* const* d_in, const int* in_sizes, int n_in,
                              void* d_out, int out_size)
{
    CParams cp;
    WParams wp;
    const float* priors;

    bool interleaved = (n_in == 31) && (in_sizes[2] == 24);
    if (interleaved) {
        for (int s = 0; s < 6; s++) {
            cp.feat[s] = (const float*)d_in[s * 5 + 0];
            wp.lw[s]   = (const float*)d_in[s * 5 + 1];
            cp.lb[s]   = (const float*)d_in[s * 5 + 2];
            wp.cw[s]   = (const float*)d_in[s * 5 + 3];
            cp.cb[s]   = (const float*)d_in[s * 5 + 4];
        }
        priors = (const float*)d_in[30];
    } else {
        for (int s = 0; s < 6; s++) {
            cp.feat[s] = (const float*)d_in[s];
            wp.lw[s]   = (const float*)d_in[6 + s];
            cp.lb[s]   = (const float*)d_in[12 + s];
            wp.cw[s]   = (const float*)d_in[18 + s];
            cp.cb[s]   = (const float*)d_in[24 + s];
        }
        priors = (const float*)d_in[30];
    }

    cudaFuncSetAttribute(ssd_tf32_kernel,
                         cudaFuncAttributeMaxDynamicSharedMemorySize, SMEM_BYTES);

    prep_weights<<<TOTAL_WCHUNKS, 256>>>(wp);
    ssd_tf32_kernel<<<TOTAL_BLOCKS, NTH, SMEM_BYTES>>>(cp, priors, (float*)d_out);
}

// round 11
// speedup vs baseline: 9.5541x; 1.1529x over previous
#include <cuda_runtime.h>
#include <cuda_bf16.h>
#include <stdint.h>

// ---------------------------------------------------------------------------
// SSD head via mma.sync m16n8k8 TF32, round 11:
//  - 8 warps / 256 thr: warp = 4 m-tiles x 5 n-tiles (B padded to 160 rows)
//    -> B fragment reuse x4, LDSM traffic -35%.
//  - A gather remapped: thread = (pixel, 32 k's) -> warp-LDG = 32 consecutive
//    pixels at one k-plane (fully coalesced).
//  - smem rows RS=256 with XOR-(row&7) 16B-granule swizzle: conflict-free
//    LDSM *and* conflict-free A-store STS.
// Double-buffered (cp.async B + pipelined A gather). Epilogue fused.
// ---------------------------------------------------------------------------

#define NUM_PRIORS 11640
#define NTH 256
#define RS 256                          // smem row stride bytes (16 granules)
#define NB 160                          // padded output channels (20 n-tiles)
#define ATILE (128 * RS)                // 32768
#define BTILE (NB * RS)                 // 40960
#define TOTAL_WCHUNKS 396
#define TOTAL_BLOCKS 488
#define A_OFF 0
#define B_OFF ATILE
#define BUFSZ (ATILE + BTILE)           // 73728
#define SMEM_BYTES (2 * BUFSZ)          // 147456
#define DSTRIDE 161

__device__ __constant__ int d_C[6]    = {512,1024,512,256,256,256};
__device__ __constant__ int d_logC[6] = {9,10,9,8,8,8};
__device__ __constant__ int d_F[6]    = {38,19,10,5,3,1};
__device__ __constant__ int d_FF[6]   = {1444,361,100,25,9,1};
__device__ __constant__ int d_N[6]    = {46208,11552,3200,800,288,32};
__device__ __constant__ int d_nch[6]  = {72,144,72,36,36,36};
__device__ __constant__ int d_wch0[6] = {0,72,216,288,324,360};
__device__ __constant__ int d_poff[6] = {0,8664,10830,11430,11580,11634};
__device__ __constant__ int d_bstart[7] = {0,91,452,477,484,487,488};
__device__ __constant__ int d_border[6] = {1,0,2,3,4,5};

__device__ unsigned char g_wbf[(size_t)TOTAL_WCHUNKS * BTILE];

struct WParams { const float* lw[6]; const float* cw[6]; };
struct CParams { const float* feat[6]; const float* lb[6]; const float* cb[6]; };

// ---- PTX helpers ------------------------------------------------------------
__device__ __forceinline__ uint32_t smaddr(const void* p) {
    return (uint32_t)__cvta_generic_to_shared(p);
}
__device__ __forceinline__ uint32_t to_tf32(float x) {
    uint32_t u;
    asm("cvt.rna.tf32.f32 %0, %1;" : "=r"(u) : "f"(x));
    return u;
}
__device__ __forceinline__ void ldsm4(uint32_t* r, uint32_t a) {
    asm volatile("ldmatrix.sync.aligned.m8n8.x4.shared.b16 {%0,%1,%2,%3}, [%4];"
                 : "=r"(r[0]), "=r"(r[1]), "=r"(r[2]), "=r"(r[3]) : "r"(a));
}
__device__ __forceinline__ void ldsm2(uint32_t* r, uint32_t a) {
    asm volatile("ldmatrix.sync.aligned.m8n8.x2.shared.b16 {%0,%1}, [%2];"
                 : "=r"(r[0]), "=r"(r[1]) : "r"(a));
}
__device__ __forceinline__ void mma_tf32(float* d, const uint32_t* a, const uint32_t* b) {
    asm volatile("mma.sync.aligned.m16n8k8.row.col.f32.tf32.tf32.f32 "
                 "{%0,%1,%2,%3},{%4,%5,%6,%7},{%8,%9},{%0,%1,%2,%3};"
                 : "+f"(d[0]), "+f"(d[1]), "+f"(d[2]), "+f"(d[3])
                 : "r"(a[0]), "r"(a[1]), "r"(a[2]), "r"(a[3]),
                   "r"(b[0]), "r"(b[1]));
}
__device__ __forceinline__ void cpasync16(uint32_t dst, const void* src) {
    asm volatile("cp.async.cg.shared.global [%0], [%1], 16;"
                 :: "r"(dst), "l"(src) : "memory");
}
__device__ __forceinline__ void cpcommit() {
    asm volatile("cp.async.commit_group;" ::: "memory");
}
__device__ __forceinline__ void cpwait0() {
    asm volatile("cp.async.wait_group 0;" ::: "memory");
}

// swizzled byte offset of (row, 16B-granule g) within a tile
__device__ __forceinline__ uint32_t swz(uint32_t row, uint32_t g) {
    return row * RS + ((g ^ (row & 7u)) << 4);
}

// ---- weight preprocessing: RNA tf32, kk-major, swizzled rows ---------------
__global__ __launch_bounds__(256) void prep_weights(WParams P)
{
    int ch = blockIdx.x;
    int s = 0;
    #pragma unroll
    for (int i = 1; i < 6; i++) if (ch >= d_wch0[i]) s = i;
    int cis = ch - d_wch0[s];
    int C = d_C[s];
    int K = C * 9;
    int k0 = cis * 64;
    int kk = k0 >> d_logC[s];
    int c0 = k0 & (C - 1);
    size_t base = (size_t)ch * BTILE;

    for (int e = threadIdx.x; e < NB * 64; e += blockDim.x) {
        int row = e >> 6;
        int col = e & 63;
        float v = 0.f;
        if (row < 150) {
            int widx = (c0 + col) * 9 + kk;
            v = (row < 24) ? P.lw[s][(size_t)row * K + widx]
                           : P.cw[s][(size_t)(row - 24) * K + widx];
        }
        uint32_t off = swz(row, col >> 2) + (col & 3) * 4;
        *(uint32_t*)(g_wbf + base + off) = to_tf32(v);
    }
}

// ---- main fused kernel --------------------------------------------------------
__global__ __launch_bounds__(NTH, 1) void ssd_tf32_kernel(
    CParams P, const float* __restrict__ priors, float* __restrict__ out)
{
    extern __shared__ __align__(16) unsigned char sm[];
    float* Dsm = (float*)sm;
    const uint32_t smb = smaddr(sm);

    const int tid = threadIdx.x;
    const int wid = tid >> 5;
    const int lane = tid & 31;
    const int mg = wid & 1;               // m-group: 64 pixels (4 m-tiles)
    const int ng = wid >> 1;              // n-group: 5 tiles
    const int gbase = ng * 5;

    // ---- block -> (stage, pixel tile) ----
    int bid = blockIdx.x;
    int oi = 0;
    #pragma unroll
    for (int i = 1; i < 6; i++) if (bid >= d_bstart[i]) oi = i;
    const int s = d_border[oi];
    const int pix0 = (bid - d_bstart[oi]) * 128;

    const int C = d_C[s], logC = d_logC[s], F = d_F[s], FF = d_FF[s], N = d_N[s];
    const int nch = d_nch[s], wch0 = d_wch0[s];
    const float* __restrict__ feat = P.feat[s];

    // ---- A gather: thread = one pixel, 32 k-values (kq half) ----
    const int arow = tid & 127;             // pixel row in tile
    const int kq   = tid >> 7;              // 0 or 1: k offset 0/32
    const int apix = pix0 + arow;
    const bool aok = (apix < N);
    int ab = 0, ay = 0, ax = 0;
    if (aok) {
        ab = apix / FF;
        int r = apix - ab * FF;
        ay = r / F;
        ax = r - ay * F;
    }
    const float* fb0 = feat + (size_t)ab * C * FF;

    // ---- ldmatrix lane components ----
    const int a_mloc = (lane & 7) + ((lane >> 3) & 1) * 8;   // row within m-tile
    const int a_kg   = lane >> 4;                             // granule half
    const int b_r    = lane & 7;
    const int b_half = (lane >> 3) & 1;
    const int b_tl   = (lane >> 4) & 1;

    float acc[4][5][4];
    #pragma unroll
    for (int mt = 0; mt < 4; mt++)
        #pragma unroll
        for (int nt = 0; nt < 5; nt++)
            #pragma unroll
            for (int q = 0; q < 4; q++) acc[mt][nt][q] = 0.f;

    // ---------------- helpers ----------------
    auto copyB = [&](int ch, int buf) {
        const uint4* src = (const uint4*)(g_wbf + (size_t)(wch0 + ch) * BTILE);
        uint32_t dst = smb + buf * BUFSZ + B_OFF;
        #pragma unroll
        for (int i = tid; i < BTILE / 16; i += NTH)
            cpasync16(dst + i * 16, src + i);
    };
    float xg[32];
    auto gatherA = [&](int ch) {
        int k0 = ch * 64;
        int kk = k0 >> logC;
        int c0 = k0 & (C - 1);
        int ky = kk / 3, kx = kk - ky * 3;
        int iy = ay + ky - 1, ix = ax + kx - 1;
        bool v = aok && ((unsigned)iy < (unsigned)F) && ((unsigned)ix < (unsigned)F);
        const float* bp = fb0 + (size_t)(c0 + kq * 32) * FF + iy * F + ix;
        #pragma unroll
        for (int j = 0; j < 32; j++)
            xg[j] = v ? __ldg(bp + (size_t)j * FF) : 0.f;
    };
    auto storeA = [&](int buf) {
        uint32_t base = smb + buf * BUFSZ + A_OFF;
        #pragma unroll
        for (int g = 0; g < 8; g++) {                 // 8 granules of 4 values
            uint32_t t0 = to_tf32(xg[g * 4 + 0]);
            uint32_t t1 = to_tf32(xg[g * 4 + 1]);
            uint32_t t2 = to_tf32(xg[g * 4 + 2]);
            uint32_t t3 = to_tf32(xg[g * 4 + 3]);
            uint32_t off = swz((uint32_t)arow, (uint32_t)(kq * 8 + g));
            asm volatile("st.shared.v4.b32 [%0], {%1,%2,%3,%4};"
                         :: "r"(base + off), "r"(t0), "r"(t1), "r"(t2), "r"(t3)
                         : "memory");
        }
    };
    auto compute = [&](int buf) {
        const uint32_t aB = smb + buf * BUFSZ + A_OFF;
        const uint32_t bB = smb + buf * BUFSZ + B_OFF;
        // per-lane row bases + swizzle masks (hoisted)
        uint32_t abase[4], amask[4];
        #pragma unroll
        for (int mt = 0; mt < 4; mt++) {
            uint32_t r = (uint32_t)(mg * 64 + mt * 16 + a_mloc);
            abase[mt] = aB + r * RS;
            amask[mt] = r & 7u;
        }
        uint32_t bbase[2], bmask[2], b2base, b2mask;
        #pragma unroll
        for (int p = 0; p < 2; p++) {
            uint32_t r = (uint32_t)((gbase + p * 2 + b_tl) * 8 + b_r);
            bbase[p] = bB + r * RS;
            bmask[p] = r & 7u;
        }
        {
            uint32_t r = (uint32_t)((gbase + 4) * 8 + b_r);
            b2base = bB + r * RS;
            b2mask = r & 7u;
        }
        #pragma unroll
        for (int k8 = 0; k8 < 8; k8++) {
            const uint32_t g0 = (uint32_t)k8 * 2;
            uint32_t a[4][4];
            #pragma unroll
            for (int mt = 0; mt < 4; mt++)
                ldsm4(a[mt], abase[mt] + (((g0 + a_kg) ^ amask[mt]) << 4));
            uint32_t b0[4], b1[4], b2[2];
            ldsm4(b0, bbase[0] + (((g0 + b_half) ^ bmask[0]) << 4));
            ldsm4(b1, bbase[1] + (((g0 + b_half) ^ bmask[1]) << 4));
            ldsm2(b2, b2base + (((g0 + b_half) ^ b2mask) << 4));
            #pragma unroll
            for (int mt = 0; mt < 4; mt++) {
                mma_tf32(acc[mt][0], a[mt], b0);
                mma_tf32(acc[mt][1], a[mt], b0 + 2);
                mma_tf32(acc[mt][2], a[mt], b1);
                mma_tf32(acc[mt][3], a[mt], b1 + 2);
                mma_tf32(acc[mt][4], a[mt], b2);
            }
        }
    };

    // ---------------- pipeline ----------------
    copyB(0, 0);
    cpcommit();
    gatherA(0);
    storeA(0);
    cpwait0();
    __syncthreads();

    for (int ch = 0; ch < nch; ch++) {
        int cur = ch & 1;
        bool pf = (ch + 1 < nch);
        if (pf) {
            copyB(ch + 1, cur ^ 1);
            cpcommit();
            gatherA(ch + 1);        // LDGs in flight during MMAs
        }
        compute(cur);
        if (pf) storeA(cur ^ 1);    // round + STS after MMAs
        cpwait0();
        __syncthreads();
    }

    // ---- write accumulators to smem D[128][DSTRIDE] ----
    #pragma unroll
    for (int mt = 0; mt < 4; mt++)
        #pragma unroll
        for (int nt = 0; nt < 5; nt++) {
            int r = mg * 64 + mt * 16 + (lane >> 2);
            int c = (gbase + nt) * 8 + (lane & 3) * 2;
            Dsm[r * DSTRIDE + c]           = acc[mt][nt][0];
            Dsm[r * DSTRIDE + c + 1]       = acc[mt][nt][1];
            Dsm[(r + 8) * DSTRIDE + c]     = acc[mt][nt][2];
            Dsm[(r + 8) * DSTRIDE + c + 1] = acc[mt][nt][3];
        }
    __syncthreads();

    // ---- per-pixel bias + decode + softmax ----
    if (tid < 128) {
        int n = pix0 + tid;
        if (n < N) {
            const float* drow = Dsm + tid * DSTRIDE;
            int b = n / FF;
            int r = n - b * FF;
            int pbase = d_poff[s] + r * 6;
            float* ob = out + ((size_t)b * NUM_PRIORS + pbase) * 25;
            const float* lb = P.lb[s];
            const float* cb = P.cb[s];
            #pragma unroll
            for (int pic = 0; pic < 6; pic++) {
                const float* pr = priors + (size_t)(pbase + pic) * 4;
                float prx = __ldg(pr + 0), pry = __ldg(pr + 1);
                float prz = __ldg(pr + 2), prw = __ldg(pr + 3);
                float lx = drow[pic * 4 + 0] + __ldg(lb + pic * 4 + 0);
                float ly = drow[pic * 4 + 1] + __ldg(lb + pic * 4 + 1);
                float lw_ = drow[pic * 4 + 2] + __ldg(lb + pic * 4 + 2);
                float lh_ = drow[pic * 4 + 3] + __ldg(lb + pic * 4 + 3);
                float cx = prx + lx * 0.1f * prz;
                float cy = pry + ly * 0.1f * prw;
                float w = prz * expf(lw_ * 0.2f);
                float h = prw * expf(lh_ * 0.2f);
                float mnx = cx - 0.5f * w;
                float mny = cy - 0.5f * h;
                float* o = ob + pic * 25;
                o[0] = mnx; o[1] = mny; o[2] = mnx + w; o[3] = mny + h;

                float vv[21];
                float mx = -1e30f;
                #pragma unroll
                for (int c2 = 0; c2 < 21; c2++) {
                    vv[c2] = drow[24 + pic * 21 + c2] + __ldg(cb + pic * 21 + c2);
                    mx = fmaxf(mx, vv[c2]);
                }
                float ssum = 0.f;
                #pragma unroll
                for (int c2 = 0; c2 < 21; c2++) { vv[c2] = expf(vv[c2] - mx); ssum += vv[c2]; }
                float inv = 1.f / ssum;
                #pragma unroll
                for (int c2 = 0; c2 < 21; c2++) o[4 + c2] = vv[c2] * inv;
            }
        }
    }
}

// ---------------------------------------------------------------------------
extern "C" void kernel_launch(void* const* d_in, const int* in_sizes, int n_in,
                              void* d_out, int out_size)
{
    CParams cp;
    WParams wp;
    const float* priors;

    bool interleaved = (n_in == 31) && (in_sizes[2] == 24);
    if (interleaved) {
        for (int s = 0; s < 6; s++) {
            cp.feat[s] = (const float*)d_in[s * 5 + 0];
            wp.lw[s]   = (const float*)d_in[s * 5 + 1];
            cp.lb[s]   = (const float*)d_in[s * 5 + 2];
            wp.cw[s]   = (const float*)d_in[s * 5 + 3];
            cp.cb[s]   = (const float*)d_in[s * 5 + 4];
        }
        priors = (const float*)d_in[30];
    } else {
        for (int s = 0; s < 6; s++) {
            cp.feat[s] = (const float*)d_in[s];
            wp.lw[s]   = (const float*)d_in[6 + s];
            cp.lb[s]   = (const float*)d_in[12 + s];
            wp.cw[s]   = (const float*)d_in[18 + s];
            cp.cb[s]   = (const float*)d_in[24 + s];
        }
        priors = (const float*)d_in[30];
    }

    cudaFuncSetAttribute(ssd_tf32_kernel,
                         cudaFuncAttributeMaxDynamicSharedMemorySize, SMEM_BYTES);

    prep_weights<<<TOTAL_WCHUNKS, 256>>>(wp);
    ssd_tf32_kernel<<<TOTAL_BLOCKS, NTH, SMEM_BYTES>>>(cp, priors, (float*)d_out);
}

// round 12
// speedup vs baseline: 9.8130x; 1.0271x over previous
#include <cuda_runtime.h>
#include <cuda_bf16.h>
#include <stdint.h>

// ---------------------------------------------------------------------------
// SSD head via mma.sync m16n8k8 TF32, round 12:
// 512 threads / 16 warps (4 per SMSP) to fill the tensor pipe, keeping the
// round-11 wins: XOR-granule swizzled smem (conflict-free LDSM + STS),
// fully coalesced A gather, NB=160 padded B. Warp = 2 m-tiles x 5 n-tiles.
// Double-buffered (cp.async B + pipelined A gather). Epilogue fused.
// ---------------------------------------------------------------------------

#define NUM_PRIORS 11640
#define NTH 512
#define RS 256                          // smem row stride bytes (16 granules)
#define NB 160                          // padded output channels (20 n-tiles)
#define ATILE (128 * RS)                // 32768
#define BTILE (NB * RS)                 // 40960
#define TOTAL_WCHUNKS 396
#define TOTAL_BLOCKS 488
#define A_OFF 0
#define B_OFF ATILE
#define BUFSZ (ATILE + BTILE)           // 73728
#define SMEM_BYTES (2 * BUFSZ)          // 147456
#define DSTRIDE 161

__device__ __constant__ int d_C[6]    = {512,1024,512,256,256,256};
__device__ __constant__ int d_logC[6] = {9,10,9,8,8,8};
__device__ __constant__ int d_F[6]    = {38,19,10,5,3,1};
__device__ __constant__ int d_FF[6]   = {1444,361,100,25,9,1};
__device__ __constant__ int d_N[6]    = {46208,11552,3200,800,288,32};
__device__ __constant__ int d_nch[6]  = {72,144,72,36,36,36};
__device__ __constant__ int d_wch0[6] = {0,72,216,288,324,360};
__device__ __constant__ int d_poff[6] = {0,8664,10830,11430,11580,11634};
__device__ __constant__ int d_bstart[7] = {0,91,452,477,484,487,488};
__device__ __constant__ int d_border[6] = {1,0,2,3,4,5};

__device__ unsigned char g_wbf[(size_t)TOTAL_WCHUNKS * BTILE];

struct WParams { const float* lw[6]; const float* cw[6]; };
struct CParams { const float* feat[6]; const float* lb[6]; const float* cb[6]; };

// ---- PTX helpers ------------------------------------------------------------
__device__ __forceinline__ uint32_t smaddr(const void* p) {
    return (uint32_t)__cvta_generic_to_shared(p);
}
__device__ __forceinline__ uint32_t to_tf32(float x) {
    uint32_t u;
    asm("cvt.rna.tf32.f32 %0, %1;" : "=r"(u) : "f"(x));
    return u;
}
__device__ __forceinline__ void ldsm4(uint32_t* r, uint32_t a) {
    asm volatile("ldmatrix.sync.aligned.m8n8.x4.shared.b16 {%0,%1,%2,%3}, [%4];"
                 : "=r"(r[0]), "=r"(r[1]), "=r"(r[2]), "=r"(r[3]) : "r"(a));
}
__device__ __forceinline__ void ldsm2(uint32_t* r, uint32_t a) {
    asm volatile("ldmatrix.sync.aligned.m8n8.x2.shared.b16 {%0,%1}, [%2];"
                 : "=r"(r[0]), "=r"(r[1]) : "r"(a));
}
__device__ __forceinline__ void mma_tf32(float* d, const uint32_t* a, const uint32_t* b) {
    asm volatile("mma.sync.aligned.m16n8k8.row.col.f32.tf32.tf32.f32 "
                 "{%0,%1,%2,%3},{%4,%5,%6,%7},{%8,%9},{%0,%1,%2,%3};"
                 : "+f"(d[0]), "+f"(d[1]), "+f"(d[2]), "+f"(d[3])
                 : "r"(a[0]), "r"(a[1]), "r"(a[2]), "r"(a[3]),
                   "r"(b[0]), "r"(b[1]));
}
__device__ __forceinline__ void cpasync16(uint32_t dst, const void* src) {
    asm volatile("cp.async.cg.shared.global [%0], [%1], 16;"
                 :: "r"(dst), "l"(src) : "memory");
}
__device__ __forceinline__ void cpcommit() {
    asm volatile("cp.async.commit_group;" ::: "memory");
}
__device__ __forceinline__ void cpwait0() {
    asm volatile("cp.async.wait_group 0;" ::: "memory");
}

// swizzled byte offset of (row, 16B-granule g) within a tile
__device__ __forceinline__ uint32_t swz(uint32_t row, uint32_t g) {
    return row * RS + ((g ^ (row & 7u)) << 4);
}

// ---- weight preprocessing: RNA tf32, kk-major, swizzled rows ---------------
__global__ __launch_bounds__(256) void prep_weights(WParams P)
{
    int ch = blockIdx.x;
    int s = 0;
    #pragma unroll
    for (int i = 1; i < 6; i++) if (ch >= d_wch0[i]) s = i;
    int cis = ch - d_wch0[s];
    int C = d_C[s];
    int K = C * 9;
    int k0 = cis * 64;
    int kk = k0 >> d_logC[s];
    int c0 = k0 & (C - 1);
    size_t base = (size_t)ch * BTILE;

    for (int e = threadIdx.x; e < NB * 64; e += blockDim.x) {
        int row = e >> 6;
        int col = e & 63;
        float v = 0.f;
        if (row < 150) {
            int widx = (c0 + col) * 9 + kk;
            v = (row < 24) ? P.lw[s][(size_t)row * K + widx]
                           : P.cw[s][(size_t)(row - 24) * K + widx];
        }
        uint32_t off = swz(row, col >> 2) + (col & 3) * 4;
        *(uint32_t*)(g_wbf + base + off) = to_tf32(v);
    }
}

// ---- main fused kernel --------------------------------------------------------
__global__ __launch_bounds__(NTH, 1) void ssd_tf32_kernel(
    CParams P, const float* __restrict__ priors, float* __restrict__ out)
{
    extern __shared__ __align__(16) unsigned char sm[];
    float* Dsm = (float*)sm;
    const uint32_t smb = smaddr(sm);

    const int tid = threadIdx.x;
    const int wid = tid >> 5;
    const int lane = tid & 31;
    const int mg = wid & 3;               // m-group: 32 pixels (2 m-tiles)
    const int ng = wid >> 2;              // n-group: 5 tiles
    const int gbase = ng * 5;

    // ---- block -> (stage, pixel tile) ----
    int bid = blockIdx.x;
    int oi = 0;
    #pragma unroll
    for (int i = 1; i < 6; i++) if (bid >= d_bstart[i]) oi = i;
    const int s = d_border[oi];
    const int pix0 = (bid - d_bstart[oi]) * 128;

    const int C = d_C[s], logC = d_logC[s], F = d_F[s], FF = d_FF[s], N = d_N[s];
    const int nch = d_nch[s], wch0 = d_wch0[s];
    const float* __restrict__ feat = P.feat[s];

    // ---- A gather: 4 threads per pixel, 16 k-values each (coalesced) ----
    const int arow = tid & 127;             // pixel row in tile
    const int kq   = tid >> 7;              // 0..3: k offset 0/16/32/48
    const int apix = pix0 + arow;
    const bool aok = (apix < N);
    int ab = 0, ay = 0, ax = 0;
    if (aok) {
        ab = apix / FF;
        int r = apix - ab * FF;
        ay = r / F;
        ax = r - ay * F;
    }
    const float* fb0 = feat + (size_t)ab * C * FF;

    // ---- ldmatrix lane components ----
    const int a_mloc = (lane & 7) + ((lane >> 3) & 1) * 8;   // row within m-tile
    const int a_kg   = lane >> 4;                             // granule half
    const int b_r    = lane & 7;
    const int b_half = (lane >> 3) & 1;
    const int b_tl   = (lane >> 4) & 1;

    float acc[2][5][4];
    #pragma unroll
    for (int mt = 0; mt < 2; mt++)
        #pragma unroll
        for (int nt = 0; nt < 5; nt++)
            #pragma unroll
            for (int q = 0; q < 4; q++) acc[mt][nt][q] = 0.f;

    // ---------------- helpers ----------------
    auto copyB = [&](int ch, int buf) {
        const uint4* src = (const uint4*)(g_wbf + (size_t)(wch0 + ch) * BTILE);
        uint32_t dst = smb + buf * BUFSZ + B_OFF;
        #pragma unroll
        for (int i = tid; i < BTILE / 16; i += NTH)
            cpasync16(dst + i * 16, src + i);
    };
    float xg[16];
    auto gatherA = [&](int ch) {
        int k0 = ch * 64;
        int kk = k0 >> logC;
        int c0 = k0 & (C - 1);
        int ky = kk / 3, kx = kk - ky * 3;
        int iy = ay + ky - 1, ix = ax + kx - 1;
        bool v = aok && ((unsigned)iy < (unsigned)F) && ((unsigned)ix < (unsigned)F);
        const float* bp = fb0 + (size_t)(c0 + kq * 16) * FF + iy * F + ix;
        #pragma unroll
        for (int j = 0; j < 16; j++)
            xg[j] = v ? __ldg(bp + (size_t)j * FF) : 0.f;
    };
    auto storeA = [&](int buf) {
        uint32_t base = smb + buf * BUFSZ + A_OFF;
        #pragma unroll
        for (int g = 0; g < 4; g++) {                 // 4 granules of 4 values
            uint32_t t0 = to_tf32(xg[g * 4 + 0]);
            uint32_t t1 = to_tf32(xg[g * 4 + 1]);
            uint32_t t2 = to_tf32(xg[g * 4 + 2]);
            uint32_t t3 = to_tf32(xg[g * 4 + 3]);
            uint32_t off = swz((uint32_t)arow, (uint32_t)(kq * 4 + g));
            asm volatile("st.shared.v4.b32 [%0], {%1,%2,%3,%4};"
                         :: "r"(base + off), "r"(t0), "r"(t1), "r"(t2), "r"(t3)
                         : "memory");
        }
    };
    auto compute = [&](int buf) {
        const uint32_t aB = smb + buf * BUFSZ + A_OFF;
        const uint32_t bB = smb + buf * BUFSZ + B_OFF;
        // hoisted per-lane row bases + swizzle masks
        uint32_t abase[2], amask[2];
        #pragma unroll
        for (int mt = 0; mt < 2; mt++) {
            uint32_t r = (uint32_t)(mg * 32 + mt * 16 + a_mloc);
            abase[mt] = aB + r * RS;
            amask[mt] = r & 7u;
        }
        uint32_t bbase[2], bmask[2], b2base, b2mask;
        #pragma unroll
        for (int p = 0; p < 2; p++) {
            uint32_t r = (uint32_t)((gbase + p * 2 + b_tl) * 8 + b_r);
            bbase[p] = bB + r * RS;
            bmask[p] = r & 7u;
        }
        {
            uint32_t r = (uint32_t)((gbase + 4) * 8 + b_r);
            b2base = bB + r * RS;
            b2mask = r & 7u;
        }
        #pragma unroll
        for (int k8 = 0; k8 < 8; k8++) {
            const uint32_t g0 = (uint32_t)k8 * 2;
            uint32_t a0[4], a1[4];
            ldsm4(a0, abase[0] + (((g0 + a_kg) ^ amask[0]) << 4));
            ldsm4(a1, abase[1] + (((g0 + a_kg) ^ amask[1]) << 4));
            uint32_t b0[4], b1[4], b2[2];
            ldsm4(b0, bbase[0] + (((g0 + b_half) ^ bmask[0]) << 4));
            ldsm4(b1, bbase[1] + (((g0 + b_half) ^ bmask[1]) << 4));
            ldsm2(b2, b2base + (((g0 + b_half) ^ b2mask) << 4));
            mma_tf32(acc[0][0], a0, b0);
            mma_tf32(acc[1][0], a1, b0);
            mma_tf32(acc[0][1], a0, b0 + 2);
            mma_tf32(acc[1][1], a1, b0 + 2);
            mma_tf32(acc[0][2], a0, b1);
            mma_tf32(acc[1][2], a1, b1);
            mma_tf32(acc[0][3], a0, b1 + 2);
            mma_tf32(acc[1][3], a1, b1 + 2);
            mma_tf32(acc[0][4], a0, b2);
            mma_tf32(acc[1][4], a1, b2);
        }
    };

    // ---------------- pipeline ----------------
    copyB(0, 0);
    cpcommit();
    gatherA(0);
    storeA(0);
    cpwait0();
    __syncthreads();

    for (int ch = 0; ch < nch; ch++) {
        int cur = ch & 1;
        bool pf = (ch + 1 < nch);
        if (pf) {
            copyB(ch + 1, cur ^ 1);
            cpcommit();
            gatherA(ch + 1);        // LDGs in flight during MMAs
        }
        compute(cur);
        if (pf) storeA(cur ^ 1);    // round + STS after MMAs
        cpwait0();
        __syncthreads();
    }

    // ---- write accumulators to smem D[128][DSTRIDE] ----
    #pragma unroll
    for (int mt = 0; mt < 2; mt++)
        #pragma unroll
        for (int nt = 0; nt < 5; nt++) {
            int r = mg * 32 + mt * 16 + (lane >> 2);
            int c = (gbase + nt) * 8 + (lane & 3) * 2;
            Dsm[r * DSTRIDE + c]           = acc[mt][nt][0];
            Dsm[r * DSTRIDE + c + 1]       = acc[mt][nt][1];
            Dsm[(r + 8) * DSTRIDE + c]     = acc[mt][nt][2];
            Dsm[(r + 8) * DSTRIDE + c + 1] = acc[mt][nt][3];
        }
    __syncthreads();

    // ---- per-pixel bias + decode + softmax ----
    if (tid < 128) {
        int n = pix0 + tid;
        if (n < N) {
            const float* drow = Dsm + tid * DSTRIDE;
            int b = n / FF;
            int r = n - b * FF;
            int pbase = d_poff[s] + r * 6;
            float* ob = out + ((size_t)b * NUM_PRIORS + pbase) * 25;
            const float* lb = P.lb[s];
            const float* cb = P.cb[s];
            #pragma unroll
            for (int pic = 0; pic < 6; pic++) {
                const float* pr = priors + (size_t)(pbase + pic) * 4;
                float prx = __ldg(pr + 0), pry = __ldg(pr + 1);
                float prz = __ldg(pr + 2), prw = __ldg(pr + 3);
                float lx = drow[pic * 4 + 0] + __ldg(lb + pic * 4 + 0);
                float ly = drow[pic * 4 + 1] + __ldg(lb + pic * 4 + 1);
                float lw_ = drow[pic * 4 + 2] + __ldg(lb + pic * 4 + 2);
                float lh_ = drow[pic * 4 + 3] + __ldg(lb + pic * 4 + 3);
                float cx = prx + lx * 0.1f * prz;
                float cy = pry + ly * 0.1f * prw;
                float w = prz * expf(lw_ * 0.2f);
                float h = prw * expf(lh_ * 0.2f);
                float mnx = cx - 0.5f * w;
                float mny = cy - 0.5f * h;
                float* o = ob + pic * 25;
                o[0] = mnx; o[1] = mny; o[2] = mnx + w; o[3] = mny + h;

                float vv[21];
                float mx = -1e30f;
                #pragma unroll
                for (int c2 = 0; c2 < 21; c2++) {
                    vv[c2] = drow[24 + pic * 21 + c2] + __ldg(cb + pic * 21 + c2);
                    mx = fmaxf(mx, vv[c2]);
                }
                float ssum = 0.f;
                #pragma unroll
                for (int c2 = 0; c2 < 21; c2++) { vv[c2] = expf(vv[c2] - mx); ssum += vv[c2]; }
                float inv = 1.f / ssum;
                #pragma unroll
                for (int c2 = 0; c2 < 21; c2++) o[4 + c2] = vv[c2] * inv;
            }
        }
    }
}

// ---------------------------------------------------------------------------
extern "C" void kernel_launch(void* const* d_in, const int* in_sizes, int n_in,
                              void* d_out, int out_size)
{
    CParams cp;
    WParams wp;
    const float* priors;

    bool interleaved = (n_in == 31) && (in_sizes[2] == 24);
    if (interleaved) {
        for (int s = 0; s < 6; s++) {
            cp.feat[s] = (const float*)d_in[s * 5 + 0];
            wp.lw[s]   = (const float*)d_in[s * 5 + 1];
            cp.lb[s]   = (const float*)d_in[s * 5 + 2];
            wp.cw[s]   = (const float*)d_in[s * 5 + 3];
            cp.cb[s]   = (const float*)d_in[s * 5 + 4];
        }
        priors = (const float*)d_in[30];
    } else {
        for (int s = 0; s < 6; s++) {
            cp.feat[s] = (const float*)d_in[s];
            wp.lw[s]   = (const float*)d_in[6 + s];
            cp.lb[s]   = (const float*)d_in[12 + s];
            wp.cw[s]   = (const float*)d_in[18 + s];
            cp.cb[s]   = (const float*)d_in[24 + s];
        }
        priors = (const float*)d_in[30];
    }

    cudaFuncSetAttribute(ssd_tf32_kernel,
                         cudaFuncAttributeMaxDynamicSharedMemorySize, SMEM_BYTES);

    prep_weights<<<TOTAL_WCHUNKS, 256>>>(wp);
    ssd_tf32_kernel<<<TOTAL_BLOCKS, NTH, SMEM_BYTES>>>(cp, priors, (float*)d_out);
}